// round 4
// baseline (speedup 1.0000x reference)
#include <cuda_runtime.h>
#include <cstdint>

#define HH 96
#define WW 96
#define CC 512
#define DD 64
#define N_POS 73728   // 8*96*96

// ---------------- scratch (device globals: no allocations allowed) ----------
__device__ float g_q[N_POS * DD];
__device__ float g_k[N_POS * DD];
__device__ float g_v[N_POS * CC];
__device__ float g_accv[N_POS * CC];
__device__ float g_mv[N_POS];
__device__ float g_lv[N_POS];

// ---------------- tf32 mma / ldmatrix helpers --------------------------------
__device__ __forceinline__ uint32_t f2tf32(float f) {
    uint32_t u;
    asm("cvt.rna.tf32.f32 %0, %1;" : "=r"(u) : "f"(f));
    return u;
}

__device__ __forceinline__ void mma_tf32(float* c, const uint32_t* a, const uint32_t* b) {
    asm volatile(
        "mma.sync.aligned.m16n8k8.row.col.f32.tf32.tf32.f32 "
        "{%0,%1,%2,%3}, {%4,%5,%6,%7}, {%8,%9}, {%0,%1,%2,%3};\n"
        : "+f"(c[0]), "+f"(c[1]), "+f"(c[2]), "+f"(c[3])
        : "r"(a[0]), "r"(a[1]), "r"(a[2]), "r"(a[3]),
          "r"(b[0]), "r"(b[1]));
}

__device__ __forceinline__ uint32_t s2u(const void* p) {
    return (uint32_t)__cvta_generic_to_shared(p);
}

__device__ __forceinline__ void ldsm4(uint32_t* r, uint32_t addr) {
    asm volatile("ldmatrix.sync.aligned.m8n8.x4.shared.b16 {%0,%1,%2,%3}, [%4];"
        : "=r"(r[0]), "=r"(r[1]), "=r"(r[2]), "=r"(r[3]) : "r"(addr));
}

__device__ __forceinline__ void ldsm2(uint32_t* r, uint32_t addr) {
    asm volatile("ldmatrix.sync.aligned.m8n8.x2.shared.b16 {%0,%1}, [%2];"
        : "=r"(r[0]), "=r"(r[1]) : "r"(addr));
}

// ---------------- Kernel 1: fused QKV projection GEMM (tf32 + ldmatrix) -----
// Grid: (10, 576). Col-tile 0 -> q, 1 -> k, 2..9 -> v cols (ct-2)*64.
// 128x64 tile, K-chunk 32. A row-major tf32, B transposed (n-major) tf32.
__global__ __launch_bounds__(256) void qkv_gemm(
    const float* __restrict__ x,
    const float* __restrict__ Wq, const float* __restrict__ bq,
    const float* __restrict__ Wk, const float* __restrict__ bk,
    const float* __restrict__ Wv, const float* __restrict__ bv)
{
    __shared__ uint32_t As[128][36];
    __shared__ uint32_t Bt[64][36];   // [n][k]

    const int ct = blockIdx.x;
    const int rowBase = blockIdx.y * 128;

    const float* W; const float* bias; float* dst; int ldw, coff;
    if (ct == 0)      { W = Wq; bias = bq; dst = g_q; ldw = 64;  coff = 0; }
    else if (ct == 1) { W = Wk; bias = bk; dst = g_k; ldw = 64;  coff = 0; }
    else              { W = Wv; bias = bv; dst = g_v; ldw = CC;  coff = (ct - 2) * 64; }

    const int tid  = threadIdx.x;
    const int lane = tid & 31;
    const int warp = tid >> 5;
    const int wm   = warp & 3;   // M sub-tile (32 rows)
    const int wn   = warp >> 2;  // N sub-tile (32 cols)
    const int g8   = lane >> 2;
    const int t4   = lane & 3;

    const int arow = tid >> 3;          // 0..31 (x4 groups of 32 rows)
    const int acol = (tid & 7) * 4;
    const int brow = tid >> 4;          // 0..15 (x2 groups of 16 k-rows)
    const int bcol = (tid & 15) * 4;    // n

    // ldmatrix per-thread byte offsets (fixed parts)
    const uint32_t asBase = s2u(&As[0][0]);
    const uint32_t btBase = s2u(&Bt[0][0]);
    uint32_t aOff[2], bOff[2];
    #pragma unroll
    for (int mi = 0; mi < 2; ++mi)
        aOff[mi] = ((wm * 32 + mi * 16 + (lane & 15)) * 36 + 4 * (lane >> 4)) * 4;
    #pragma unroll
    for (int g = 0; g < 2; ++g)
        bOff[g] = ((wn * 32 + g * 16 + ((lane & 16) >> 1) + (lane & 7)) * 36
                   + 4 * ((lane >> 3) & 1)) * 4;

    float acc[2][4][4] = {};
    float4 pA[4]; float4 pB[2];

    #pragma unroll
    for (int i = 0; i < 4; ++i)
        pA[i] = *(const float4*)(x + (size_t)(rowBase + arow + i * 32) * CC + acol);
    #pragma unroll
    for (int i = 0; i < 2; ++i)
        pB[i] = *(const float4*)(W + (size_t)(brow + i * 16) * ldw + coff + bcol);

    for (int k0 = 0; k0 < CC; k0 += 32) {
        #pragma unroll
        for (int i = 0; i < 4; ++i) {
            uint4 u = { f2tf32(pA[i].x), f2tf32(pA[i].y), f2tf32(pA[i].z), f2tf32(pA[i].w) };
            *(uint4*)&As[arow + i * 32][acol] = u;
        }
        #pragma unroll
        for (int i = 0; i < 2; ++i) {
            Bt[bcol + 0][brow + i * 16] = f2tf32(pB[i].x);
            Bt[bcol + 1][brow + i * 16] = f2tf32(pB[i].y);
            Bt[bcol + 2][brow + i * 16] = f2tf32(pB[i].z);
            Bt[bcol + 3][brow + i * 16] = f2tf32(pB[i].w);
        }
        __syncthreads();

        if (k0 + 32 < CC) {
            #pragma unroll
            for (int i = 0; i < 4; ++i)
                pA[i] = *(const float4*)(x + (size_t)(rowBase + arow + i * 32) * CC + k0 + 32 + acol);
            #pragma unroll
            for (int i = 0; i < 2; ++i)
                pB[i] = *(const float4*)(W + (size_t)(k0 + 32 + brow + i * 16) * ldw + coff + bcol);
        }

        #pragma unroll
        for (int kk = 0; kk < 4; ++kk) {
            const uint32_t kbB = kk * 32;   // 8 elems * 4B
            uint32_t a0[4], a1[4], b01[4], b23[4];
            ldsm4(a0, asBase + aOff[0] + kbB);
            ldsm4(a1, asBase + aOff[1] + kbB);
            ldsm4(b01, btBase + bOff[0] + kbB);
            ldsm4(b23, btBase + bOff[1] + kbB);
            mma_tf32(acc[0][0], a0, b01);     mma_tf32(acc[0][1], a0, b01 + 2);
            mma_tf32(acc[0][2], a0, b23);     mma_tf32(acc[0][3], a0, b23 + 2);
            mma_tf32(acc[1][0], a1, b01);     mma_tf32(acc[1][1], a1, b01 + 2);
            mma_tf32(acc[1][2], a1, b23);     mma_tf32(acc[1][3], a1, b23 + 2);
        }
        __syncthreads();
    }

    #pragma unroll
    for (int ni = 0; ni < 4; ++ni) {
        const int col = coff + wn * 32 + ni * 8 + 2 * t4;
        const float b0 = bias[col], b1 = bias[col + 1];
        #pragma unroll
        for (int mi = 0; mi < 2; ++mi) {
            const int r0 = rowBase + wm * 32 + mi * 16 + g8;
            float2 o0 = { acc[mi][ni][0] + b0, acc[mi][ni][1] + b1 };
            float2 o1 = { acc[mi][ni][2] + b0, acc[mi][ni][3] + b1 };
            *(float2*)(dst + (size_t)r0 * ldw + col) = o0;
            *(float2*)(dst + (size_t)(r0 + 8) * ldw + col) = o1;
        }
    }
}

// ---------------- shared-memory layout for attention kernels ----------------
// floats:
// [0 .. 7296)        Qs  (96 x 76, tf32 bits)   -- overlaid by Vt (128x108=13824)
// [7296 .. 14592)    Kt  (96 x 76, tf32 bits)   -- (overlay continues)
// [14592 .. 24960)   Ps  (96 x 108) fp32 scores -> tf32 bits after softmax
// [24960 .. 25344)   stats: ms, ls, fv, fh
#define QS_STRIDE 76
#define PS_STRIDE 108
#define VT_STRIDE 108
#define SM_KT   7296
#define SM_PS   14592
#define SM_MS   24960
#define SM_LS   25056
#define SM_FV   25152
#define SM_FH   25248
#define SMEM_FLOATS 25344
#define SMEM_BYTES  (SMEM_FLOATS * 4)

// ---------------- Kernel 2: column attention pass (per (b,w)) ---------------
__global__ __launch_bounds__(256, 2) void col_attn()
{
    extern __shared__ float sm[];
    uint32_t* Qs  = (uint32_t*)sm;
    uint32_t* Kt  = (uint32_t*)(sm + SM_KT);
    float*    Ps  = sm + SM_PS;
    uint32_t* Psu = (uint32_t*)Ps;
    uint32_t* Vt  = (uint32_t*)sm;   // overlays Qs+Kt

    const int tid = threadIdx.x;
    const int lane = tid & 31;
    const int warp = tid >> 5;
    const int g8 = lane >> 2, t4 = lane & 3;
    const int b = blockIdx.x / WW;
    const int w = blockIdx.x % WW;

    const uint32_t qBase = s2u(Qs), kBase = s2u(Kt), pBase = s2u(Psu), vBase = s2u(Vt);

    // ---- load Q,K (tf32 bits, [pos][dim], stride 76) ----
    for (int idx = tid; idx < HH * 16; idx += 256) {
        int pos = idx >> 4, c4 = (idx & 15) * 4;
        size_t off = (size_t)((b * HH + pos) * WW + w) * DD + c4;
        float4 q4 = *(const float4*)(g_q + off);
        float4 k4 = *(const float4*)(g_k + off);
        uint4 qu = { f2tf32(q4.x), f2tf32(q4.y), f2tf32(q4.z), f2tf32(q4.w) };
        uint4 ku = { f2tf32(k4.x), f2tf32(k4.y), f2tf32(k4.z), f2tf32(k4.w) };
        *(uint4*)&Qs[pos * QS_STRIDE + c4] = qu;
        *(uint4*)&Kt[pos * QS_STRIDE + c4] = ku;
    }
    __syncthreads();

    // ---- scores S = Q @ K^T via tf32 MMA: warps 2(M) x 4(N), tile 48x24 ----
    {
        const int sm0 = (warp & 1) * 48, sn0 = (warp >> 1) * 24;
        uint32_t qOff[3];
        #pragma unroll
        for (int mi = 0; mi < 3; ++mi)
            qOff[mi] = ((sm0 + mi * 16 + (lane & 15)) * QS_STRIDE + 4 * (lane >> 4)) * 4;
        const uint32_t kOff01 = ((sn0 + ((lane & 16) >> 1) + (lane & 7)) * QS_STRIDE
                                 + 4 * ((lane >> 3) & 1)) * 4;
        const uint32_t kOff2  = ((sn0 + 16 + (lane & 7)) * QS_STRIDE
                                 + 4 * ((lane >> 3) & 1)) * 4;

        float acc[3][3][4] = {};
        #pragma unroll
        for (int ks = 0; ks < 8; ++ks) {
            const uint32_t kbB = ks * 32;
            uint32_t a[3][4], b01[4], b2[2];
            ldsm4(a[0], qBase + qOff[0] + kbB);
            ldsm4(a[1], qBase + qOff[1] + kbB);
            ldsm4(a[2], qBase + qOff[2] + kbB);
            ldsm4(b01, kBase + kOff01 + kbB);
            ldsm2(b2,  kBase + kOff2  + kbB);
            #pragma unroll
            for (int mi = 0; mi < 3; ++mi) {
                mma_tf32(acc[mi][0], a[mi], b01);
                mma_tf32(acc[mi][1], a[mi], b01 + 2);
                mma_tf32(acc[mi][2], a[mi], b2);
            }
        }

        // write fp32 scores with diagonal mask
        #pragma unroll
        for (int mi = 0; mi < 3; ++mi) {
            const int r0 = sm0 + mi * 16 + g8, r1 = r0 + 8;
            #pragma unroll
            for (int ni = 0; ni < 3; ++ni) {
                const int c0 = sn0 + ni * 8 + 2 * t4, c1 = c0 + 1;
                Ps[r0 * PS_STRIDE + c0] = (r0 == c0) ? -1e30f : acc[mi][ni][0];
                Ps[r0 * PS_STRIDE + c1] = (r0 == c1) ? -1e30f : acc[mi][ni][1];
                Ps[r1 * PS_STRIDE + c0] = (r1 == c0) ? -1e30f : acc[mi][ni][2];
                Ps[r1 * PS_STRIDE + c1] = (r1 == c1) ? -1e30f : acc[mi][ni][3];
            }
        }
    }
    __syncthreads();

    // ---- softmax: stats + in-place convert P to tf32 bits ----
    for (int h = warp; h < HH; h += 8) {
        float m = -3.4e38f;
        for (int g = lane; g < HH; g += 32) m = fmaxf(m, Ps[h * PS_STRIDE + g]);
        #pragma unroll
        for (int o = 16; o; o >>= 1) m = fmaxf(m, __shfl_xor_sync(0xffffffffu, m, o));
        float l = 0.f;
        for (int g = lane; g < HH; g += 32) {
            uint32_t u = f2tf32(__expf(Ps[h * PS_STRIDE + g] - m));
            Psu[h * PS_STRIDE + g] = u;
            l += __uint_as_float(u);
        }
        #pragma unroll
        for (int o = 16; o; o >>= 1) l += __shfl_xor_sync(0xffffffffu, l, o);
        if (lane == 0) {
            int n = (b * HH + h) * WW + w;
            g_mv[n] = m;
            g_lv[n] = l;
        }
    }

    // ---- acc_v = P @ V via tf32 MMA: warps 2(M) x 4(N), tile 48x32 ----
    const int pm0 = (warp & 1) * 48, pn0 = (warp >> 1) * 32;
    uint32_t pOff[3], vOff[2];
    #pragma unroll
    for (int mi = 0; mi < 3; ++mi)
        pOff[mi] = ((pm0 + mi * 16 + (lane & 15)) * PS_STRIDE + 4 * (lane >> 4)) * 4;
    #pragma unroll
    for (int g = 0; g < 2; ++g)
        vOff[g] = ((pn0 + g * 16 + ((lane & 16) >> 1) + (lane & 7)) * VT_STRIDE
                   + 4 * ((lane >> 3) & 1)) * 4;

    for (int c0 = 0; c0 < CC; c0 += 128) {
        __syncthreads();
        // fill Vt[chan][key] (tf32 bits)
        for (int idx = tid; idx < HH * 32; idx += 256) {
            int gg = idx >> 5, c4 = (idx & 31) * 4;
            float4 v = *(const float4*)(g_v + (size_t)((b * HH + gg) * WW + w) * CC + c0 + c4);
            Vt[(c4 + 0) * VT_STRIDE + gg] = f2tf32(v.x);
            Vt[(c4 + 1) * VT_STRIDE + gg] = f2tf32(v.y);
            Vt[(c4 + 2) * VT_STRIDE + gg] = f2tf32(v.z);
            Vt[(c4 + 3) * VT_STRIDE + gg] = f2tf32(v.w);
        }
        __syncthreads();

        float acc[3][4][4] = {};
        #pragma unroll
        for (int ks = 0; ks < 12; ++ks) {
            const uint32_t kbB = ks * 32;
            uint32_t a[3][4], bv[2][4];
            ldsm4(a[0], pBase + pOff[0] + kbB);
            ldsm4(a[1], pBase + pOff[1] + kbB);
            ldsm4(a[2], pBase + pOff[2] + kbB);
            ldsm4(bv[0], vBase + vOff[0] + kbB);
            ldsm4(bv[1], vBase + vOff[1] + kbB);
            #pragma unroll
            for (int mi = 0; mi < 3; ++mi) {
                mma_tf32(acc[mi][0], a[mi], bv[0]);
                mma_tf32(acc[mi][1], a[mi], bv[0] + 2);
                mma_tf32(acc[mi][2], a[mi], bv[1]);
                mma_tf32(acc[mi][3], a[mi], bv[1] + 2);
            }
        }

        #pragma unroll
        for (int mi = 0; mi < 3; ++mi) {
            const int rA = pm0 + mi * 16 + g8;
            const size_t nA = (size_t)((b * HH + rA    ) * WW + w) * CC;
            const size_t nB = (size_t)((b * HH + rA + 8) * WW + w) * CC;
            #pragma unroll
            for (int ni = 0; ni < 4; ++ni) {
                const int col = c0 + pn0 + ni * 8 + 2 * t4;
                float2 o0 = { acc[mi][ni][0], acc[mi][ni][1] };
                float2 o1 = { acc[mi][ni][2], acc[mi][ni][3] };
                *(float2*)(g_accv + nA + col) = o0;
                *(float2*)(g_accv + nB + col) = o1;
            }
        }
    }
}

// ---------------- Kernel 3: row attention pass + combine (per (b,h)) --------
__global__ __launch_bounds__(256, 2) void row_attn(
    const float* __restrict__ x, const float* __restrict__ gammap,
    float* __restrict__ out)
{
    extern __shared__ float sm[];
    uint32_t* Qs  = (uint32_t*)sm;
    uint32_t* Kt  = (uint32_t*)(sm + SM_KT);
    float*    Ps  = sm + SM_PS;
    uint32_t* Psu = (uint32_t*)Ps;
    uint32_t* Vt  = (uint32_t*)sm;
    float* ms = sm + SM_MS;
    float* ls = sm + SM_LS;
    float* fv = sm + SM_FV;
    float* fh = sm + SM_FH;

    const int tid = threadIdx.x;
    const int lane = tid & 31;
    const int warp = tid >> 5;
    const int g8 = lane >> 2, t4 = lane & 3;
    const int b = blockIdx.x / HH;
    const int h = blockIdx.x % HH;
    const int nbase = (b * HH + h) * WW;

    const uint32_t qBase = s2u(Qs), kBase = s2u(Kt), pBase = s2u(Psu), vBase = s2u(Vt);

    for (int idx = tid; idx < WW * 16; idx += 256) {
        int pos = idx >> 4, c4 = (idx & 15) * 4;
        size_t off = (size_t)(nbase + pos) * DD + c4;
        float4 q4 = *(const float4*)(g_q + off);
        float4 k4 = *(const float4*)(g_k + off);
        uint4 qu = { f2tf32(q4.x), f2tf32(q4.y), f2tf32(q4.z), f2tf32(q4.w) };
        uint4 ku = { f2tf32(k4.x), f2tf32(k4.y), f2tf32(k4.z), f2tf32(k4.w) };
        *(uint4*)&Qs[pos * QS_STRIDE + c4] = qu;
        *(uint4*)&Kt[pos * QS_STRIDE + c4] = ku;
    }
    if (tid < WW) {
        fv[tid] = g_mv[nbase + tid];
        fh[tid] = g_lv[nbase + tid];
    }
    __syncthreads();

    // scores (no mask)
    {
        const int sm0 = (warp & 1) * 48, sn0 = (warp >> 1) * 24;
        uint32_t qOff[3];
        #pragma unroll
        for (int mi = 0; mi < 3; ++mi)
            qOff[mi] = ((sm0 + mi * 16 + (lane & 15)) * QS_STRIDE + 4 * (lane >> 4)) * 4;
        const uint32_t kOff01 = ((sn0 + ((lane & 16) >> 1) + (lane & 7)) * QS_STRIDE
                                 + 4 * ((lane >> 3) & 1)) * 4;
        const uint32_t kOff2  = ((sn0 + 16 + (lane & 7)) * QS_STRIDE
                                 + 4 * ((lane >> 3) & 1)) * 4;

        float acc[3][3][4] = {};
        #pragma unroll
        for (int ks = 0; ks < 8; ++ks) {
            const uint32_t kbB = ks * 32;
            uint32_t a[3][4], b01[4], b2[2];
            ldsm4(a[0], qBase + qOff[0] + kbB);
            ldsm4(a[1], qBase + qOff[1] + kbB);
            ldsm4(a[2], qBase + qOff[2] + kbB);
            ldsm4(b01, kBase + kOff01 + kbB);
            ldsm2(b2,  kBase + kOff2  + kbB);
            #pragma unroll
            for (int mi = 0; mi < 3; ++mi) {
                mma_tf32(acc[mi][0], a[mi], b01);
                mma_tf32(acc[mi][1], a[mi], b01 + 2);
                mma_tf32(acc[mi][2], a[mi], b2);
            }
        }

        #pragma unroll
        for (int mi = 0; mi < 3; ++mi) {
            const int r0 = sm0 + mi * 16 + g8, r1 = r0 + 8;
            #pragma unroll
            for (int ni = 0; ni < 3; ++ni) {
                const int c0 = sn0 + ni * 8 + 2 * t4;
                *(float2*)&Ps[r0 * PS_STRIDE + c0] = *(float2*)&acc[mi][ni][0];
                *(float2*)&Ps[r1 * PS_STRIDE + c0] = *(float2*)&acc[mi][ni][2];
            }
        }
    }
    __syncthreads();

    for (int wq = warp; wq < WW; wq += 8) {
        float m = -3.4e38f;
        for (int g = lane; g < WW; g += 32) m = fmaxf(m, Ps[wq * PS_STRIDE + g]);
        #pragma unroll
        for (int o = 16; o; o >>= 1) m = fmaxf(m, __shfl_xor_sync(0xffffffffu, m, o));
        float l = 0.f;
        for (int g = lane; g < WW; g += 32) {
            uint32_t u = f2tf32(__expf(Ps[wq * PS_STRIDE + g] - m));
            Psu[wq * PS_STRIDE + g] = u;
            l += __uint_as_float(u);
        }
        #pragma unroll
        for (int o = 16; o; o >>= 1) l += __shfl_xor_sync(0xffffffffu, l, o);
        if (lane == 0) { ms[wq] = m; ls[wq] = l; }
    }
    __syncthreads();

    if (tid < WW) {
        float mh = ms[tid], lh = ls[tid];
        float mv = fv[tid], lv = fh[tid];
        float M  = fmaxf(mh, mv);
        float ev = __expf(mv - M), eh = __expf(mh - M);
        float inv = 1.f / (ev * lv + eh * lh);
        fv[tid] = ev * inv;
        fh[tid] = eh * inv;
    }

    const float gamma = *gammap;
    const int pm0 = (warp & 1) * 48, pn0 = (warp >> 1) * 32;
    uint32_t pOff[3], vOff[2];
    #pragma unroll
    for (int mi = 0; mi < 3; ++mi)
        pOff[mi] = ((pm0 + mi * 16 + (lane & 15)) * PS_STRIDE + 4 * (lane >> 4)) * 4;
    #pragma unroll
    for (int g = 0; g < 2; ++g)
        vOff[g] = ((pn0 + g * 16 + ((lane & 16) >> 1) + (lane & 7)) * VT_STRIDE
                   + 4 * ((lane >> 3) & 1)) * 4;

    for (int c0 = 0; c0 < CC; c0 += 128) {
        __syncthreads();
        for (int idx = tid; idx < WW * 32; idx += 256) {
            int u0 = idx >> 5, c4 = (idx & 31) * 4;
            float4 v = *(const float4*)(g_v + (size_t)(nbase + u0) * CC + c0 + c4);
            Vt[(c4 + 0) * VT_STRIDE + u0] = f2tf32(v.x);
            Vt[(c4 + 1) * VT_STRIDE + u0] = f2tf32(v.y);
            Vt[(c4 + 2) * VT_STRIDE + u0] = f2tf32(v.z);
            Vt[(c4 + 3) * VT_STRIDE + u0] = f2tf32(v.w);
        }
        __syncthreads();

        float acc[3][4][4] = {};
        #pragma unroll
        for (int ks = 0; ks < 12; ++ks) {
            const uint32_t kbB = ks * 32;
            uint32_t a[3][4], bv[2][4];
            ldsm4(a[0], pBase + pOff[0] + kbB);
            ldsm4(a[1], pBase + pOff[1] + kbB);
            ldsm4(a[2], pBase + pOff[2] + kbB);
            ldsm4(bv[0], vBase + vOff[0] + kbB);
            ldsm4(bv[1], vBase + vOff[1] + kbB);
            #pragma unroll
            for (int mi = 0; mi < 3; ++mi) {
                mma_tf32(acc[mi][0], a[mi], bv[0]);
                mma_tf32(acc[mi][1], a[mi], bv[0] + 2);
                mma_tf32(acc[mi][2], a[mi], bv[1]);
                mma_tf32(acc[mi][3], a[mi], bv[1] + 2);
            }
        }

        #pragma unroll
        for (int mi = 0; mi < 3; ++mi) {
            const int rA = pm0 + mi * 16 + g8;
            const int rB = rA + 8;
            const float fvA = fv[rA], fhA = fh[rA];
            const float fvB = fv[rB], fhB = fh[rB];
            const size_t oA = (size_t)(nbase + rA) * CC;
            const size_t oB = (size_t)(nbase + rB) * CC;
            #pragma unroll
            for (int ni = 0; ni < 4; ++ni) {
                const int col = c0 + pn0 + ni * 8 + 2 * t4;
                float2 avA = *(const float2*)(g_accv + oA + col);
                float2 xvA = *(const float2*)(x + oA + col);
                float2 avB = *(const float2*)(g_accv + oB + col);
                float2 xvB = *(const float2*)(x + oB + col);
                float2 o0, o1;
                o0.x = xvA.x + gamma * (fvA * avA.x + fhA * acc[mi][ni][0]);
                o0.y = xvA.y + gamma * (fvA * avA.y + fhA * acc[mi][ni][1]);
                o1.x = xvB.x + gamma * (fvB * avB.x + fhB * acc[mi][ni][2]);
                o1.y = xvB.y + gamma * (fvB * avB.y + fhB * acc[mi][ni][3]);
                *(float2*)(out + oA + col) = o0;
                *(float2*)(out + oB + col) = o1;
            }
        }
    }
}

// ---------------- launch ----------------------------------------------------
extern "C" void kernel_launch(void* const* d_in, const int* in_sizes, int n_in,
                              void* d_out, int out_size)
{
    const float* x  = (const float*)d_in[0];
    const float* Wq = (const float*)d_in[1];
    const float* bq = (const float*)d_in[2];
    const float* Wk = (const float*)d_in[3];
    const float* bk = (const float*)d_in[4];
    const float* Wv = (const float*)d_in[5];
    const float* bv = (const float*)d_in[6];
    const float* gm = (const float*)d_in[7];
    float* out = (float*)d_out;

    cudaFuncSetAttribute(col_attn, cudaFuncAttributeMaxDynamicSharedMemorySize, SMEM_BYTES);
    cudaFuncSetAttribute(row_attn, cudaFuncAttributeMaxDynamicSharedMemorySize, SMEM_BYTES);

    dim3 gA(10, 576);
    qkv_gemm<<<gA, 256>>>(x, Wq, bq, Wk, bk, Wv, bv);
    col_attn<<<768, 256, SMEM_BYTES>>>();
    row_attn<<<768, 256, SMEM_BYTES>>>(x, gm, out);
}

// round 6
// speedup vs baseline: 1.3820x; 1.3820x over previous
#include <cuda_runtime.h>
#include <cstdint>

#define HH 96
#define WW 96
#define CC 512
#define DD 64
#define N_POS 73728   // 8*96*96

// ---------------- scratch (device globals: no allocations allowed) ----------
__device__ float g_q[N_POS * DD];
__device__ float g_k[N_POS * DD];
__device__ float g_v[N_POS * CC];
__device__ float g_accv[N_POS * CC];
__device__ float g_mv[N_POS];
__device__ float g_lv[N_POS];

// ---------------- tf32 mma / ldmatrix helpers --------------------------------
__device__ __forceinline__ uint32_t f2tf32(float f) {
    uint32_t u;
    asm("cvt.rna.tf32.f32 %0, %1;" : "=r"(u) : "f"(f));
    return u;
}

__device__ __forceinline__ void mma_tf32(float* c, const uint32_t* a, const uint32_t* b) {
    asm volatile(
        "mma.sync.aligned.m16n8k8.row.col.f32.tf32.tf32.f32 "
        "{%0,%1,%2,%3}, {%4,%5,%6,%7}, {%8,%9}, {%0,%1,%2,%3};\n"
        : "+f"(c[0]), "+f"(c[1]), "+f"(c[2]), "+f"(c[3])
        : "r"(a[0]), "r"(a[1]), "r"(a[2]), "r"(a[3]),
          "r"(b[0]), "r"(b[1]));
}

__device__ __forceinline__ uint32_t s2u(const void* p) {
    return (uint32_t)__cvta_generic_to_shared(p);
}

__device__ __forceinline__ void ldsm4(uint32_t* r, uint32_t addr) {
    asm volatile("ldmatrix.sync.aligned.m8n8.x4.shared.b16 {%0,%1,%2,%3}, [%4];"
        : "=r"(r[0]), "=r"(r[1]), "=r"(r[2]), "=r"(r[3]) : "r"(addr));
}

__device__ __forceinline__ void ldsm2(uint32_t* r, uint32_t addr) {
    asm volatile("ldmatrix.sync.aligned.m8n8.x2.shared.b16 {%0,%1}, [%2];"
        : "=r"(r[0]), "=r"(r[1]) : "r"(addr));
}

// ---------------- Kernel 1: fused QKV projection GEMM (tf32 tensor) ---------
// Grid: (10, 576). Col-tile 0 -> q, 1 -> k, 2..9 -> v cols (ct-2)*64.
// 128x64 tile, K-chunk 32. A row-major tf32 (ldmatrix), B[k][n] tf32 (scalar).
__global__ __launch_bounds__(256) void qkv_gemm(
    const float* __restrict__ x,
    const float* __restrict__ Wq, const float* __restrict__ bq,
    const float* __restrict__ Wk, const float* __restrict__ bk,
    const float* __restrict__ Wv, const float* __restrict__ bv)
{
    __shared__ uint32_t As[128][36];
    __shared__ uint32_t Bs[32][68];

    const int ct = blockIdx.x;
    const int rowBase = blockIdx.y * 128;

    const float* W; const float* bias; float* dst; int ldw, coff;
    if (ct == 0)      { W = Wq; bias = bq; dst = g_q; ldw = 64;  coff = 0; }
    else if (ct == 1) { W = Wk; bias = bk; dst = g_k; ldw = 64;  coff = 0; }
    else              { W = Wv; bias = bv; dst = g_v; ldw = CC;  coff = (ct - 2) * 64; }

    const int tid  = threadIdx.x;
    const int lane = tid & 31;
    const int warp = tid >> 5;
    const int wm   = warp & 3;   // M sub-tile (32 rows)
    const int wn   = warp >> 2;  // N sub-tile (32 cols)
    const int g8   = lane >> 2;
    const int t4   = lane & 3;

    const int arow = tid >> 3;          // 0..31 (x4 groups of 32 rows)
    const int acol = (tid & 7) * 4;
    const int brow = tid >> 4;          // 0..15 (x2 groups of 16 k-rows)
    const int bcol = (tid & 15) * 4;

    const uint32_t asBase = s2u(&As[0][0]);
    uint32_t aOff[2];
    #pragma unroll
    for (int mi = 0; mi < 2; ++mi)
        aOff[mi] = ((wm * 32 + mi * 16 + (lane & 15)) * 36 + 4 * (lane >> 4)) * 4;

    float acc[2][4][4] = {};
    float4 pA[4]; float4 pB[2];

    #pragma unroll
    for (int i = 0; i < 4; ++i)
        pA[i] = *(const float4*)(x + (size_t)(rowBase + arow + i * 32) * CC + acol);
    #pragma unroll
    for (int i = 0; i < 2; ++i)
        pB[i] = *(const float4*)(W + (size_t)(brow + i * 16) * ldw + coff + bcol);

    for (int k0 = 0; k0 < CC; k0 += 32) {
        #pragma unroll
        for (int i = 0; i < 4; ++i) {
            uint4 u = { f2tf32(pA[i].x), f2tf32(pA[i].y), f2tf32(pA[i].z), f2tf32(pA[i].w) };
            *(uint4*)&As[arow + i * 32][acol] = u;
        }
        #pragma unroll
        for (int i = 0; i < 2; ++i) {
            uint4 u = { f2tf32(pB[i].x), f2tf32(pB[i].y), f2tf32(pB[i].z), f2tf32(pB[i].w) };
            *(uint4*)&Bs[brow + i * 16][bcol] = u;
        }
        __syncthreads();

        if (k0 + 32 < CC) {
            #pragma unroll
            for (int i = 0; i < 4; ++i)
                pA[i] = *(const float4*)(x + (size_t)(rowBase + arow + i * 32) * CC + k0 + 32 + acol);
            #pragma unroll
            for (int i = 0; i < 2; ++i)
                pB[i] = *(const float4*)(W + (size_t)(k0 + 32 + brow + i * 16) * ldw + coff + bcol);
        }

        #pragma unroll
        for (int kk = 0; kk < 4; ++kk) {
            const int kb = kk * 8;
            const uint32_t kbB = kk * 32;
            uint32_t a0[4], a1[4], bfrag[4][2];
            ldsm4(a0, asBase + aOff[0] + kbB);
            ldsm4(a1, asBase + aOff[1] + kbB);
            #pragma unroll
            for (int ni = 0; ni < 4; ++ni) {
                const int n = wn * 32 + ni * 8 + g8;
                bfrag[ni][0] = Bs[kb + t4    ][n];
                bfrag[ni][1] = Bs[kb + t4 + 4][n];
            }
            #pragma unroll
            for (int ni = 0; ni < 4; ++ni) {
                mma_tf32(acc[0][ni], a0, bfrag[ni]);
                mma_tf32(acc[1][ni], a1, bfrag[ni]);
            }
        }
        __syncthreads();
    }

    #pragma unroll
    for (int ni = 0; ni < 4; ++ni) {
        const int col = coff + wn * 32 + ni * 8 + 2 * t4;
        const float b0 = bias[col], b1 = bias[col + 1];
        #pragma unroll
        for (int mi = 0; mi < 2; ++mi) {
            const int r0 = rowBase + wm * 32 + mi * 16 + g8;
            float2 o0 = { acc[mi][ni][0] + b0, acc[mi][ni][1] + b1 };
            float2 o1 = { acc[mi][ni][2] + b0, acc[mi][ni][3] + b1 };
            *(float2*)(dst + (size_t)r0 * ldw + col) = o0;
            *(float2*)(dst + (size_t)(r0 + 8) * ldw + col) = o1;
        }
    }
}

// ---------------- shared-memory layout for attention kernels ----------------
// floats:
// [0 .. 6528)        Qs  (96 x 68, tf32 bits)   -- overlaid by Vs (96x132=12672)
// [6528 .. 13056)    Ks  (96 x 68, tf32 bits)   -- (overlay continues)
// [13056 .. 22656)   Ps  (96 x 100) fp32 scores -> tf32 bits after softmax
// [22656 .. 23040)   stats: ms, ls, fv, fh (96 each)
#define QK_STRIDE 68
#define PS_STRIDE 100
#define VS_STRIDE 132
#define SM_KS   6528
#define SM_PS   13056
#define SM_MS   22656
#define SM_LS   22752
#define SM_FV   22848
#define SM_FH   22944
#define SMEM_FLOATS 23040
#define SMEM_BYTES  (SMEM_FLOATS * 4)

// ---------------- Kernel 2: column attention pass (per (b,w)) ---------------
__global__ __launch_bounds__(256, 2) void col_attn()
{
    extern __shared__ float sm[];
    uint32_t* Qs  = (uint32_t*)sm;
    uint32_t* Ks  = (uint32_t*)(sm + SM_KS);
    float*    Ps  = sm + SM_PS;
    uint32_t* Psu = (uint32_t*)Ps;
    uint32_t* Vsu = (uint32_t*)sm;   // overlays Qs+Ks

    const int tid = threadIdx.x;
    const int lane = tid & 31;
    const int warp = tid >> 5;
    const int g8 = lane >> 2, t4 = lane & 3;
    const int b = blockIdx.x / WW;
    const int w = blockIdx.x % WW;

    const uint32_t qBase = s2u(Qs), kBase = s2u(Ks), pBase = s2u(Psu);

    // ---- load Q,K (tf32 bits, natural [pos][dim]) ----
    for (int idx = tid; idx < HH * 16; idx += 256) {
        int pos = idx >> 4, c4 = (idx & 15) * 4;
        size_t off = (size_t)((b * HH + pos) * WW + w) * DD + c4;
        float4 q4 = *(const float4*)(g_q + off);
        float4 k4 = *(const float4*)(g_k + off);
        uint4 qu = { f2tf32(q4.x), f2tf32(q4.y), f2tf32(q4.z), f2tf32(q4.w) };
        uint4 ku = { f2tf32(k4.x), f2tf32(k4.y), f2tf32(k4.z), f2tf32(k4.w) };
        *(uint4*)&Qs[pos * QK_STRIDE + c4] = qu;
        *(uint4*)&Ks[pos * QK_STRIDE + c4] = ku;
    }
    __syncthreads();

    // ---- scores S = Q @ K^T via tf32 MMA + ldmatrix: warps 2(M) x 4(N) ----
    {
        const int sm0 = (warp & 1) * 48, sn0 = (warp >> 1) * 24;
        uint32_t qOff[3];
        #pragma unroll
        for (int mi = 0; mi < 3; ++mi)
            qOff[mi] = ((sm0 + mi * 16 + (lane & 15)) * QK_STRIDE + 4 * (lane >> 4)) * 4;
        const uint32_t kOff01 = ((sn0 + ((lane & 16) >> 1) + (lane & 7)) * QK_STRIDE
                                 + 4 * ((lane >> 3) & 1)) * 4;
        const uint32_t kOff2  = ((sn0 + 16 + (lane & 7)) * QK_STRIDE
                                 + 4 * ((lane >> 3) & 1)) * 4;

        float acc[3][3][4] = {};
        #pragma unroll
        for (int ks = 0; ks < 8; ++ks) {
            const uint32_t kbB = ks * 32;
            uint32_t a[3][4], b01[4], b2[2];
            ldsm4(a[0], qBase + qOff[0] + kbB);
            ldsm4(a[1], qBase + qOff[1] + kbB);
            ldsm4(a[2], qBase + qOff[2] + kbB);
            ldsm4(b01, kBase + kOff01 + kbB);
            ldsm2(b2,  kBase + kOff2  + kbB);
            #pragma unroll
            for (int mi = 0; mi < 3; ++mi) {
                mma_tf32(acc[mi][0], a[mi], b01);
                mma_tf32(acc[mi][1], a[mi], b01 + 2);
                mma_tf32(acc[mi][2], a[mi], b2);
            }
        }

        // write fp32 scores with diagonal mask
        #pragma unroll
        for (int mi = 0; mi < 3; ++mi) {
            const int r0 = sm0 + mi * 16 + g8, r1 = r0 + 8;
            #pragma unroll
            for (int ni = 0; ni < 3; ++ni) {
                const int c0 = sn0 + ni * 8 + 2 * t4, c1 = c0 + 1;
                Ps[r0 * PS_STRIDE + c0] = (r0 == c0) ? -1e30f : acc[mi][ni][0];
                Ps[r0 * PS_STRIDE + c1] = (r0 == c1) ? -1e30f : acc[mi][ni][1];
                Ps[r1 * PS_STRIDE + c0] = (r1 == c0) ? -1e30f : acc[mi][ni][2];
                Ps[r1 * PS_STRIDE + c1] = (r1 == c1) ? -1e30f : acc[mi][ni][3];
            }
        }
    }
    __syncthreads();

    // ---- softmax: stats + in-place convert P to tf32 bits ----
    for (int h = warp; h < HH; h += 8) {
        float m = -3.4e38f;
        for (int g = lane; g < HH; g += 32) m = fmaxf(m, Ps[h * PS_STRIDE + g]);
        #pragma unroll
        for (int o = 16; o; o >>= 1) m = fmaxf(m, __shfl_xor_sync(0xffffffffu, m, o));
        float l = 0.f;
        for (int g = lane; g < HH; g += 32) {
            uint32_t u = f2tf32(__expf(Ps[h * PS_STRIDE + g] - m));
            Psu[h * PS_STRIDE + g] = u;
            l += __uint_as_float(u);
        }
        #pragma unroll
        for (int o = 16; o; o >>= 1) l += __shfl_xor_sync(0xffffffffu, l, o);
        if (lane == 0) {
            int n = (b * HH + h) * WW + w;
            g_mv[n] = m;
            g_lv[n] = l;
        }
    }

    // ---- acc_v = P @ V: ldmatrix P (A), scalar V (B); warps 2(M) x 4(N) ----
    const int pm0 = (warp & 1) * 48, pn0 = (warp >> 1) * 32;
    uint32_t pOff[3];
    #pragma unroll
    for (int mi = 0; mi < 3; ++mi)
        pOff[mi] = ((pm0 + mi * 16 + (lane & 15)) * PS_STRIDE + 4 * (lane >> 4)) * 4;

    for (int c0 = 0; c0 < CC; c0 += 128) {
        __syncthreads();
        // fill Vs natural [key][chan] (tf32 bits)
        for (int idx = tid; idx < HH * 32; idx += 256) {
            int gg = idx >> 5, c4 = (idx & 31) * 4;
            float4 v = *(const float4*)(g_v + (size_t)((b * HH + gg) * WW + w) * CC + c0 + c4);
            uint4 u = { f2tf32(v.x), f2tf32(v.y), f2tf32(v.z), f2tf32(v.w) };
            *(uint4*)(Vsu + gg * VS_STRIDE + c4) = u;
        }
        __syncthreads();

        float acc[3][4][4] = {};
        #pragma unroll
        for (int ks = 0; ks < 12; ++ks) {
            const int kb = ks * 8;
            const uint32_t kbB = ks * 32;
            uint32_t a[3][4], bf[4][2];
            ldsm4(a[0], pBase + pOff[0] + kbB);
            ldsm4(a[1], pBase + pOff[1] + kbB);
            ldsm4(a[2], pBase + pOff[2] + kbB);
            #pragma unroll
            for (int ni = 0; ni < 4; ++ni) {
                const int n = pn0 + ni * 8 + g8;
                bf[ni][0] = Vsu[(kb + t4    ) * VS_STRIDE + n];
                bf[ni][1] = Vsu[(kb + t4 + 4) * VS_STRIDE + n];
            }
            #pragma unroll
            for (int mi = 0; mi < 3; ++mi)
                #pragma unroll
                for (int ni = 0; ni < 4; ++ni)
                    mma_tf32(acc[mi][ni], a[mi], bf[ni]);
        }

        #pragma unroll
        for (int mi = 0; mi < 3; ++mi) {
            const int rA = pm0 + mi * 16 + g8;
            const size_t nA = (size_t)((b * HH + rA    ) * WW + w) * CC;
            const size_t nB = (size_t)((b * HH + rA + 8) * WW + w) * CC;
            #pragma unroll
            for (int ni = 0; ni < 4; ++ni) {
                const int col = c0 + pn0 + ni * 8 + 2 * t4;
                float2 o0 = { acc[mi][ni][0], acc[mi][ni][1] };
                float2 o1 = { acc[mi][ni][2], acc[mi][ni][3] };
                *(float2*)(g_accv + nA + col) = o0;
                *(float2*)(g_accv + nB + col) = o1;
            }
        }
    }
}

// ---------------- Kernel 3: row attention pass + combine (per (b,h)) --------
__global__ __launch_bounds__(256, 2) void row_attn(
    const float* __restrict__ x, const float* __restrict__ gammap,
    float* __restrict__ out)
{
    extern __shared__ float sm[];
    uint32_t* Qs  = (uint32_t*)sm;
    uint32_t* Ks  = (uint32_t*)(sm + SM_KS);
    float*    Ps  = sm + SM_PS;
    uint32_t* Psu = (uint32_t*)Ps;
    uint32_t* Vsu = (uint32_t*)sm;
    float* ms = sm + SM_MS;
    float* ls = sm + SM_LS;
    float* fv = sm + SM_FV;
    float* fh = sm + SM_FH;

    const int tid = threadIdx.x;
    const int lane = tid & 31;
    const int warp = tid >> 5;
    const int g8 = lane >> 2, t4 = lane & 3;
    const int b = blockIdx.x / HH;
    const int h = blockIdx.x % HH;
    const int nbase = (b * HH + h) * WW;

    const uint32_t qBase = s2u(Qs), kBase = s2u(Ks), pBase = s2u(Psu);

    for (int idx = tid; idx < WW * 16; idx += 256) {
        int pos = idx >> 4, c4 = (idx & 15) * 4;
        size_t off = (size_t)(nbase + pos) * DD + c4;
        float4 q4 = *(const float4*)(g_q + off);
        float4 k4 = *(const float4*)(g_k + off);
        uint4 qu = { f2tf32(q4.x), f2tf32(q4.y), f2tf32(q4.z), f2tf32(q4.w) };
        uint4 ku = { f2tf32(k4.x), f2tf32(k4.y), f2tf32(k4.z), f2tf32(k4.w) };
        *(uint4*)&Qs[pos * QK_STRIDE + c4] = qu;
        *(uint4*)&Ks[pos * QK_STRIDE + c4] = ku;
    }
    if (tid < WW) {
        fv[tid] = g_mv[nbase + tid];
        fh[tid] = g_lv[nbase + tid];
    }
    __syncthreads();

    // scores (no mask)
    {
        const int sm0 = (warp & 1) * 48, sn0 = (warp >> 1) * 24;
        uint32_t qOff[3];
        #pragma unroll
        for (int mi = 0; mi < 3; ++mi)
            qOff[mi] = ((sm0 + mi * 16 + (lane & 15)) * QK_STRIDE + 4 * (lane >> 4)) * 4;
        const uint32_t kOff01 = ((sn0 + ((lane & 16) >> 1) + (lane & 7)) * QK_STRIDE
                                 + 4 * ((lane >> 3) & 1)) * 4;
        const uint32_t kOff2  = ((sn0 + 16 + (lane & 7)) * QK_STRIDE
                                 + 4 * ((lane >> 3) & 1)) * 4;

        float acc[3][3][4] = {};
        #pragma unroll
        for (int ks = 0; ks < 8; ++ks) {
            const uint32_t kbB = ks * 32;
            uint32_t a[3][4], b01[4], b2[2];
            ldsm4(a[0], qBase + qOff[0] + kbB);
            ldsm4(a[1], qBase + qOff[1] + kbB);
            ldsm4(a[2], qBase + qOff[2] + kbB);
            ldsm4(b01, kBase + kOff01 + kbB);
            ldsm2(b2,  kBase + kOff2  + kbB);
            #pragma unroll
            for (int mi = 0; mi < 3; ++mi) {
                mma_tf32(acc[mi][0], a[mi], b01);
                mma_tf32(acc[mi][1], a[mi], b01 + 2);
                mma_tf32(acc[mi][2], a[mi], b2);
            }
        }

        #pragma unroll
        for (int mi = 0; mi < 3; ++mi) {
            const int r0 = sm0 + mi * 16 + g8, r1 = r0 + 8;
            #pragma unroll
            for (int ni = 0; ni < 3; ++ni) {
                const int c0 = sn0 + ni * 8 + 2 * t4;
                *(float2*)&Ps[r0 * PS_STRIDE + c0] = *(float2*)&acc[mi][ni][0];
                *(float2*)&Ps[r1 * PS_STRIDE + c0] = *(float2*)&acc[mi][ni][2];
            }
        }
    }
    __syncthreads();

    for (int wq = warp; wq < WW; wq += 8) {
        float m = -3.4e38f;
        for (int g = lane; g < WW; g += 32) m = fmaxf(m, Ps[wq * PS_STRIDE + g]);
        #pragma unroll
        for (int o = 16; o; o >>= 1) m = fmaxf(m, __shfl_xor_sync(0xffffffffu, m, o));
        float l = 0.f;
        for (int g = lane; g < WW; g += 32) {
            uint32_t u = f2tf32(__expf(Ps[wq * PS_STRIDE + g] - m));
            Psu[wq * PS_STRIDE + g] = u;
            l += __uint_as_float(u);
        }
        #pragma unroll
        for (int o = 16; o; o >>= 1) l += __shfl_xor_sync(0xffffffffu, l, o);
        if (lane == 0) { ms[wq] = m; ls[wq] = l; }
    }
    __syncthreads();

    if (tid < WW) {
        float mh = ms[tid], lh = ls[tid];
        float mv = fv[tid], lv = fh[tid];
        float M  = fmaxf(mh, mv);
        float ev = __expf(mv - M), eh = __expf(mh - M);
        float inv = 1.f / (ev * lv + eh * lh);
        fv[tid] = ev * inv;
        fh[tid] = eh * inv;
    }

    const float gamma = *gammap;
    const int pm0 = (warp & 1) * 48, pn0 = (warp >> 1) * 32;
    uint32_t pOff[3];
    #pragma unroll
    for (int mi = 0; mi < 3; ++mi)
        pOff[mi] = ((pm0 + mi * 16 + (lane & 15)) * PS_STRIDE + 4 * (lane >> 4)) * 4;

    for (int c0 = 0; c0 < CC; c0 += 128) {
        __syncthreads();
        for (int idx = tid; idx < WW * 32; idx += 256) {
            int u0 = idx >> 5, c4 = (idx & 31) * 4;
            float4 v = *(const float4*)(g_v + (size_t)(nbase + u0) * CC + c0 + c4);
            uint4 u = { f2tf32(v.x), f2tf32(v.y), f2tf32(v.z), f2tf32(v.w) };
            *(uint4*)(Vsu + u0 * VS_STRIDE + c4) = u;
        }
        __syncthreads();

        float acc[3][4][4] = {};
        #pragma unroll
        for (int ks = 0; ks < 12; ++ks) {
            const int kb = ks * 8;
            const uint32_t kbB = ks * 32;
            uint32_t a[3][4], bf[4][2];
            ldsm4(a[0], pBase + pOff[0] + kbB);
            ldsm4(a[1], pBase + pOff[1] + kbB);
            ldsm4(a[2], pBase + pOff[2] + kbB);
            #pragma unroll
            for (int ni = 0; ni < 4; ++ni) {
                const int n = pn0 + ni * 8 + g8;
                bf[ni][0] = Vsu[(kb + t4    ) * VS_STRIDE + n];
                bf[ni][1] = Vsu[(kb + t4 + 4) * VS_STRIDE + n];
            }
            #pragma unroll
            for (int mi = 0; mi < 3; ++mi)
                #pragma unroll
                for (int ni = 0; ni < 4; ++ni)
                    mma_tf32(acc[mi][ni], a[mi], bf[ni]);
        }

        #pragma unroll
        for (int mi = 0; mi < 3; ++mi) {
            const int rA = pm0 + mi * 16 + g8;
            const int rB = rA + 8;
            const float fvA = fv[rA], fhA = fh[rA];
            const float fvB = fv[rB], fhB = fh[rB];
            const size_t oA = (size_t)(nbase + rA) * CC;
            const size_t oB = (size_t)(nbase + rB) * CC;
            #pragma unroll
            for (int ni = 0; ni < 4; ++ni) {
                const int col = c0 + pn0 + ni * 8 + 2 * t4;
                float2 avA = *(const float2*)(g_accv + oA + col);
                float2 xvA = *(const float2*)(x + oA + col);
                float2 avB = *(const float2*)(g_accv + oB + col);
                float2 xvB = *(const float2*)(x + oB + col);
                float2 o0, o1;
                o0.x = xvA.x + gamma * (fvA * avA.x + fhA * acc[mi][ni][0]);
                o0.y = xvA.y + gamma * (fvA * avA.y + fhA * acc[mi][ni][1]);
                o1.x = xvB.x + gamma * (fvB * avB.x + fhB * acc[mi][ni][2]);
                o1.y = xvB.y + gamma * (fvB * avB.y + fhB * acc[mi][ni][3]);
                *(float2*)(out + oA + col) = o0;
                *(float2*)(out + oB + col) = o1;
            }
        }
    }
}

// ---------------- launch ----------------------------------------------------
extern "C" void kernel_launch(void* const* d_in, const int* in_sizes, int n_in,
                              void* d_out, int out_size)
{
    const float* x  = (const float*)d_in[0];
    const float* Wq = (const float*)d_in[1];
    const float* bq = (const float*)d_in[2];
    const float* Wk = (const float*)d_in[3];
    const float* bk = (const float*)d_in[4];
    const float* Wv = (const float*)d_in[5];
    const float* bv = (const float*)d_in[6];
    const float* gm = (const float*)d_in[7];
    float* out = (float*)d_out;

    cudaFuncSetAttribute(col_attn, cudaFuncAttributeMaxDynamicSharedMemorySize, SMEM_BYTES);
    cudaFuncSetAttribute(row_attn, cudaFuncAttributeMaxDynamicSharedMemorySize, SMEM_BYTES);

    dim3 gA(10, 576);
    qkv_gemm<<<gA, 256>>>(x, Wq, bq, Wk, bk, Wv, bv);
    col_attn<<<768, 256, SMEM_BYTES>>>();
    row_attn<<<768, 256, SMEM_BYTES>>>(x, gm, out);
}

// round 7
// speedup vs baseline: 1.6127x; 1.1669x over previous
#include <cuda_runtime.h>
#include <cstdint>

#define HH 96
#define WW 96
#define CC 512
#define DD 64
#define N_POS 73728   // 8*96*96

// ---------------- scratch (device globals: no allocations allowed) ----------
__device__ float g_q[N_POS * DD];
__device__ float g_k[N_POS * DD];
__device__ float g_v[N_POS * CC];
__device__ float g_accv[N_POS * CC];
__device__ float g_mv[N_POS];
__device__ float g_lv[N_POS];

// ---------------- tf32 mma / ldmatrix helpers --------------------------------
__device__ __forceinline__ uint32_t f2tf32(float f) {
    uint32_t u;
    asm("cvt.rna.tf32.f32 %0, %1;" : "=r"(u) : "f"(f));
    return u;
}

__device__ __forceinline__ void mma_tf32(float* c, const uint32_t* a, const uint32_t* b) {
    asm volatile(
        "mma.sync.aligned.m16n8k8.row.col.f32.tf32.tf32.f32 "
        "{%0,%1,%2,%3}, {%4,%5,%6,%7}, {%8,%9}, {%0,%1,%2,%3};\n"
        : "+f"(c[0]), "+f"(c[1]), "+f"(c[2]), "+f"(c[3])
        : "r"(a[0]), "r"(a[1]), "r"(a[2]), "r"(a[3]),
          "r"(b[0]), "r"(b[1]));
}

__device__ __forceinline__ uint32_t s2u(const void* p) {
    return (uint32_t)__cvta_generic_to_shared(p);
}

__device__ __forceinline__ void ldsm4(uint32_t* r, uint32_t addr) {
    asm volatile("ldmatrix.sync.aligned.m8n8.x4.shared.b16 {%0,%1,%2,%3}, [%4];"
        : "=r"(r[0]), "=r"(r[1]), "=r"(r[2]), "=r"(r[3]) : "r"(addr));
}

__device__ __forceinline__ void ldsm2(uint32_t* r, uint32_t addr) {
    asm volatile("ldmatrix.sync.aligned.m8n8.x2.shared.b16 {%0,%1}, [%2];"
        : "=r"(r[0]), "=r"(r[1]) : "r"(addr));
}

// ---------------- Kernel 1: fused QKV projection GEMM (tf32 tensor) ---------
// Grid: (5, 576). ct 0 -> q|k (64+64 cols), ct 1..4 -> v cols (ct-1)*128.
// Block tile 128x128, K-chunk 32. Warps 4(M) x 2(N), warp tile 32x64.
// A row-major tf32 (ldmatrix), B n-major Bs[n][k] tf32 (ldmatrix).
__global__ __launch_bounds__(256, 2) void qkv_gemm(
    const float* __restrict__ x,
    const float* __restrict__ Wq, const float* __restrict__ bq,
    const float* __restrict__ Wk, const float* __restrict__ bk,
    const float* __restrict__ Wv, const float* __restrict__ bv)
{
    __shared__ uint32_t As[128][36];   // [m][k]
    __shared__ uint32_t Bs[128][36];   // [n][k]

    const int ct = blockIdx.x;
    const int rowBase = blockIdx.y * 128;

    const int tid  = threadIdx.x;
    const int lane = tid & 31;
    const int warp = tid >> 5;
    const int wm   = warp >> 1;  // 0..3 -> rows [wm*32, +32)
    const int wn   = warp & 1;   // 0..1 -> cols [wn*64, +64)
    const int g8   = lane >> 2;
    const int t4   = lane & 3;

    // A fill mapping: 4 x (32 rows x 8 float4)
    const int arow = tid >> 3;          // 0..31
    const int acol = (tid & 7) * 4;

    // B fill mapping: thread -> n-row (tid&127), k-half (tid>>7)*16
    const int bn  = tid & 127;
    const int bkh = (tid >> 7) * 16;
    const float* wsrc; int wld;
    if (ct == 0) {
        if (bn < 64) { wsrc = Wq + bn;        wld = 64; }
        else         { wsrc = Wk + (bn - 64); wld = 64; }
    } else {
        wsrc = Wv + (ct - 1) * 128 + bn; wld = CC;
    }

    // ldmatrix offsets
    const uint32_t asBase = s2u(&As[0][0]);
    const uint32_t bsBase = s2u(&Bs[0][0]);
    uint32_t aOff[2], bOff[4];
    #pragma unroll
    for (int mi = 0; mi < 2; ++mi)
        aOff[mi] = ((wm * 32 + mi * 16 + (lane & 15)) * 36 + 4 * (lane >> 4)) * 4;
    #pragma unroll
    for (int g = 0; g < 4; ++g)
        bOff[g] = ((wn * 64 + g * 16 + ((lane & 16) >> 1) + (lane & 7)) * 36
                   + 4 * ((lane >> 3) & 1)) * 4;

    float acc[2][8][4] = {};
    float4 pA[4];

    #pragma unroll
    for (int i = 0; i < 4; ++i)
        pA[i] = *(const float4*)(x + (size_t)(rowBase + arow + i * 32) * CC + acol);

    for (int k0 = 0; k0 < CC; k0 += 32) {
        // store A (pre-converted tf32)
        #pragma unroll
        for (int i = 0; i < 4; ++i) {
            uint4 u = { f2tf32(pA[i].x), f2tf32(pA[i].y), f2tf32(pA[i].z), f2tf32(pA[i].w) };
            *(uint4*)&As[arow + i * 32][acol] = u;
        }
        // fill B n-major: 16 coalesced LDG.32 then 4 conflict-free STS.128
        {
            float wv[16];
            #pragma unroll
            for (int j = 0; j < 16; ++j)
                wv[j] = wsrc[(size_t)(k0 + bkh + j) * wld];
            #pragma unroll
            for (int jj = 0; jj < 4; ++jj) {
                uint4 u = { f2tf32(wv[jj * 4]),     f2tf32(wv[jj * 4 + 1]),
                            f2tf32(wv[jj * 4 + 2]), f2tf32(wv[jj * 4 + 3]) };
                *(uint4*)&Bs[bn][bkh + jj * 4] = u;
            }
        }
        __syncthreads();

        if (k0 + 32 < CC) {
            #pragma unroll
            for (int i = 0; i < 4; ++i)
                pA[i] = *(const float4*)(x + (size_t)(rowBase + arow + i * 32) * CC + k0 + 32 + acol);
        }

        #pragma unroll
        for (int kk = 0; kk < 4; ++kk) {
            const uint32_t kbB = kk * 32;
            uint32_t a[2][4], bf[4][4];
            ldsm4(a[0], asBase + aOff[0] + kbB);
            ldsm4(a[1], asBase + aOff[1] + kbB);
            ldsm4(bf[0], bsBase + bOff[0] + kbB);
            ldsm4(bf[1], bsBase + bOff[1] + kbB);
            ldsm4(bf[2], bsBase + bOff[2] + kbB);
            ldsm4(bf[3], bsBase + bOff[3] + kbB);
            #pragma unroll
            for (int mi = 0; mi < 2; ++mi)
                #pragma unroll
                for (int g = 0; g < 4; ++g) {
                    mma_tf32(acc[mi][g * 2    ], a[mi], bf[g]);
                    mma_tf32(acc[mi][g * 2 + 1], a[mi], bf[g] + 2);
                }
        }
        __syncthreads();
    }

    // epilogue: add bias, store. Warp's 64 cols map cleanly: ct==0 & wn==0 -> q,
    // ct==0 & wn==1 -> k, ct>=1 -> v slice.
    float* dstBase; const float* biasBase; int ldw;
    if (ct == 0) {
        if (wn == 0) { dstBase = g_q; biasBase = bq; ldw = 64; }
        else         { dstBase = g_k; biasBase = bk; ldw = 64; }
    } else {
        dstBase = g_v + (ct - 1) * 128 + wn * 64;
        biasBase = bv + (ct - 1) * 128 + wn * 64;
        ldw = CC;
    }

    #pragma unroll
    for (int ni = 0; ni < 8; ++ni) {
        const int colL = ni * 8 + 2 * t4;       // 0..62 within warp's 64
        const float b0 = biasBase[colL], b1 = biasBase[colL + 1];
        #pragma unroll
        for (int mi = 0; mi < 2; ++mi) {
            const int r0 = rowBase + wm * 32 + mi * 16 + g8;
            float2 o0 = { acc[mi][ni][0] + b0, acc[mi][ni][1] + b1 };
            float2 o1 = { acc[mi][ni][2] + b0, acc[mi][ni][3] + b1 };
            *(float2*)(dstBase + (size_t)r0 * ldw + colL) = o0;
            *(float2*)(dstBase + (size_t)(r0 + 8) * ldw + colL) = o1;
        }
    }
}

// ---------------- shared-memory layout for attention kernels ----------------
// floats:
// [0 .. 6528)        Qs  (96 x 68, tf32 bits)   -- overlaid by Vs (96x132=12672)
// [6528 .. 13056)    Ks  (96 x 68, tf32 bits)   -- (overlay continues)
// [13056 .. 22656)   Ps  (96 x 100) fp32 scores -> tf32 bits after softmax
// [22656 .. 23040)   stats: ms, ls, fv, fh (96 each)
#define QK_STRIDE 68
#define PS_STRIDE 100
#define VS_STRIDE 132
#define SM_KS   6528
#define SM_PS   13056
#define SM_MS   22656
#define SM_LS   22752
#define SM_FV   22848
#define SM_FH   22944
#define SMEM_FLOATS 23040
#define SMEM_BYTES  (SMEM_FLOATS * 4)

// ---------------- Kernel 2: column attention pass (per (b,w)) ---------------
__global__ __launch_bounds__(256, 2) void col_attn()
{
    extern __shared__ float sm[];
    uint32_t* Qs  = (uint32_t*)sm;
    uint32_t* Ks  = (uint32_t*)(sm + SM_KS);
    float*    Ps  = sm + SM_PS;
    uint32_t* Psu = (uint32_t*)Ps;
    uint32_t* Vsu = (uint32_t*)sm;   // overlays Qs+Ks

    const int tid = threadIdx.x;
    const int lane = tid & 31;
    const int warp = tid >> 5;
    const int g8 = lane >> 2, t4 = lane & 3;
    const int b = blockIdx.x / WW;
    const int w = blockIdx.x % WW;

    const uint32_t qBase = s2u(Qs), kBase = s2u(Ks), pBase = s2u(Psu);

    // ---- load Q,K (tf32 bits, natural [pos][dim]) ----
    for (int idx = tid; idx < HH * 16; idx += 256) {
        int pos = idx >> 4, c4 = (idx & 15) * 4;
        size_t off = (size_t)((b * HH + pos) * WW + w) * DD + c4;
        float4 q4 = *(const float4*)(g_q + off);
        float4 k4 = *(const float4*)(g_k + off);
        uint4 qu = { f2tf32(q4.x), f2tf32(q4.y), f2tf32(q4.z), f2tf32(q4.w) };
        uint4 ku = { f2tf32(k4.x), f2tf32(k4.y), f2tf32(k4.z), f2tf32(k4.w) };
        *(uint4*)&Qs[pos * QK_STRIDE + c4] = qu;
        *(uint4*)&Ks[pos * QK_STRIDE + c4] = ku;
    }
    __syncthreads();

    // ---- scores S = Q @ K^T via tf32 MMA + ldmatrix: warps 2(M) x 4(N) ----
    {
        const int sm0 = (warp & 1) * 48, sn0 = (warp >> 1) * 24;
        uint32_t qOff[3];
        #pragma unroll
        for (int mi = 0; mi < 3; ++mi)
            qOff[mi] = ((sm0 + mi * 16 + (lane & 15)) * QK_STRIDE + 4 * (lane >> 4)) * 4;
        const uint32_t kOff01 = ((sn0 + ((lane & 16) >> 1) + (lane & 7)) * QK_STRIDE
                                 + 4 * ((lane >> 3) & 1)) * 4;
        const uint32_t kOff2  = ((sn0 + 16 + (lane & 7)) * QK_STRIDE
                                 + 4 * ((lane >> 3) & 1)) * 4;

        float acc[3][3][4] = {};
        #pragma unroll
        for (int ks = 0; ks < 8; ++ks) {
            const uint32_t kbB = ks * 32;
            uint32_t a[3][4], b01[4], b2[2];
            ldsm4(a[0], qBase + qOff[0] + kbB);
            ldsm4(a[1], qBase + qOff[1] + kbB);
            ldsm4(a[2], qBase + qOff[2] + kbB);
            ldsm4(b01, kBase + kOff01 + kbB);
            ldsm2(b2,  kBase + kOff2  + kbB);
            #pragma unroll
            for (int mi = 0; mi < 3; ++mi) {
                mma_tf32(acc[mi][0], a[mi], b01);
                mma_tf32(acc[mi][1], a[mi], b01 + 2);
                mma_tf32(acc[mi][2], a[mi], b2);
            }
        }

        // write fp32 scores with diagonal mask
        #pragma unroll
        for (int mi = 0; mi < 3; ++mi) {
            const int r0 = sm0 + mi * 16 + g8, r1 = r0 + 8;
            #pragma unroll
            for (int ni = 0; ni < 3; ++ni) {
                const int c0 = sn0 + ni * 8 + 2 * t4, c1 = c0 + 1;
                Ps[r0 * PS_STRIDE + c0] = (r0 == c0) ? -1e30f : acc[mi][ni][0];
                Ps[r0 * PS_STRIDE + c1] = (r0 == c1) ? -1e30f : acc[mi][ni][1];
                Ps[r1 * PS_STRIDE + c0] = (r1 == c0) ? -1e30f : acc[mi][ni][2];
                Ps[r1 * PS_STRIDE + c1] = (r1 == c1) ? -1e30f : acc[mi][ni][3];
            }
        }
    }
    __syncthreads();

    // ---- softmax: stats + in-place convert P to tf32 bits ----
    for (int h = warp; h < HH; h += 8) {
        float m = -3.4e38f;
        for (int g = lane; g < HH; g += 32) m = fmaxf(m, Ps[h * PS_STRIDE + g]);
        #pragma unroll
        for (int o = 16; o; o >>= 1) m = fmaxf(m, __shfl_xor_sync(0xffffffffu, m, o));
        float l = 0.f;
        for (int g = lane; g < HH; g += 32) {
            uint32_t u = f2tf32(__expf(Ps[h * PS_STRIDE + g] - m));
            Psu[h * PS_STRIDE + g] = u;
            l += __uint_as_float(u);
        }
        #pragma unroll
        for (int o = 16; o; o >>= 1) l += __shfl_xor_sync(0xffffffffu, l, o);
        if (lane == 0) {
            int n = (b * HH + h) * WW + w;
            g_mv[n] = m;
            g_lv[n] = l;
        }
    }

    // ---- acc_v = P @ V: ldmatrix P (A), scalar V (B); warps 2(M) x 4(N) ----
    const int pm0 = (warp & 1) * 48, pn0 = (warp >> 1) * 32;
    uint32_t pOff[3];
    #pragma unroll
    for (int mi = 0; mi < 3; ++mi)
        pOff[mi] = ((pm0 + mi * 16 + (lane & 15)) * PS_STRIDE + 4 * (lane >> 4)) * 4;

    for (int c0 = 0; c0 < CC; c0 += 128) {
        __syncthreads();
        // fill Vs natural [key][chan] (tf32 bits)
        for (int idx = tid; idx < HH * 32; idx += 256) {
            int gg = idx >> 5, c4 = (idx & 31) * 4;
            float4 v = *(const float4*)(g_v + (size_t)((b * HH + gg) * WW + w) * CC + c0 + c4);
            uint4 u = { f2tf32(v.x), f2tf32(v.y), f2tf32(v.z), f2tf32(v.w) };
            *(uint4*)(Vsu + gg * VS_STRIDE + c4) = u;
        }
        __syncthreads();

        float acc[3][4][4] = {};
        #pragma unroll
        for (int ks = 0; ks < 12; ++ks) {
            const int kb = ks * 8;
            const uint32_t kbB = ks * 32;
            uint32_t a[3][4], bf[4][2];
            ldsm4(a[0], pBase + pOff[0] + kbB);
            ldsm4(a[1], pBase + pOff[1] + kbB);
            ldsm4(a[2], pBase + pOff[2] + kbB);
            #pragma unroll
            for (int ni = 0; ni < 4; ++ni) {
                const int n = pn0 + ni * 8 + g8;
                bf[ni][0] = Vsu[(kb + t4    ) * VS_STRIDE + n];
                bf[ni][1] = Vsu[(kb + t4 + 4) * VS_STRIDE + n];
            }
            #pragma unroll
            for (int mi = 0; mi < 3; ++mi)
                #pragma unroll
                for (int ni = 0; ni < 4; ++ni)
                    mma_tf32(acc[mi][ni], a[mi], bf[ni]);
        }

        #pragma unroll
        for (int mi = 0; mi < 3; ++mi) {
            const int rA = pm0 + mi * 16 + g8;
            const size_t nA = (size_t)((b * HH + rA    ) * WW + w) * CC;
            const size_t nB = (size_t)((b * HH + rA + 8) * WW + w) * CC;
            #pragma unroll
            for (int ni = 0; ni < 4; ++ni) {
                const int col = c0 + pn0 + ni * 8 + 2 * t4;
                float2 o0 = { acc[mi][ni][0], acc[mi][ni][1] };
                float2 o1 = { acc[mi][ni][2], acc[mi][ni][3] };
                *(float2*)(g_accv + nA + col) = o0;
                *(float2*)(g_accv + nB + col) = o1;
            }
        }
    }
}

// ---------------- Kernel 3: row attention pass + combine (per (b,h)) --------
__global__ __launch_bounds__(256, 2) void row_attn(
    const float* __restrict__ x, const float* __restrict__ gammap,
    float* __restrict__ out)
{
    extern __shared__ float sm[];
    uint32_t* Qs  = (uint32_t*)sm;
    uint32_t* Ks  = (uint32_t*)(sm + SM_KS);
    float*    Ps  = sm + SM_PS;
    uint32_t* Psu = (uint32_t*)Ps;
    uint32_t* Vsu = (uint32_t*)sm;
    float* ms = sm + SM_MS;
    float* ls = sm + SM_LS;
    float* fv = sm + SM_FV;
    float* fh = sm + SM_FH;

    const int tid = threadIdx.x;
    const int lane = tid & 31;
    const int warp = tid >> 5;
    const int g8 = lane >> 2, t4 = lane & 3;
    const int b = blockIdx.x / HH;
    const int h = blockIdx.x % HH;
    const int nbase = (b * HH + h) * WW;

    const uint32_t qBase = s2u(Qs), kBase = s2u(Ks), pBase = s2u(Psu);

    for (int idx = tid; idx < WW * 16; idx += 256) {
        int pos = idx >> 4, c4 = (idx & 15) * 4;
        size_t off = (size_t)(nbase + pos) * DD + c4;
        float4 q4 = *(const float4*)(g_q + off);
        float4 k4 = *(const float4*)(g_k + off);
        uint4 qu = { f2tf32(q4.x), f2tf32(q4.y), f2tf32(q4.z), f2tf32(q4.w) };
        uint4 ku = { f2tf32(k4.x), f2tf32(k4.y), f2tf32(k4.z), f2tf32(k4.w) };
        *(uint4*)&Qs[pos * QK_STRIDE + c4] = qu;
        *(uint4*)&Ks[pos * QK_STRIDE + c4] = ku;
    }
    if (tid < WW) {
        fv[tid] = g_mv[nbase + tid];
        fh[tid] = g_lv[nbase + tid];
    }
    __syncthreads();

    // scores (no mask)
    {
        const int sm0 = (warp & 1) * 48, sn0 = (warp >> 1) * 24;
        uint32_t qOff[3];
        #pragma unroll
        for (int mi = 0; mi < 3; ++mi)
            qOff[mi] = ((sm0 + mi * 16 + (lane & 15)) * QK_STRIDE + 4 * (lane >> 4)) * 4;
        const uint32_t kOff01 = ((sn0 + ((lane & 16) >> 1) + (lane & 7)) * QK_STRIDE
                                 + 4 * ((lane >> 3) & 1)) * 4;
        const uint32_t kOff2  = ((sn0 + 16 + (lane & 7)) * QK_STRIDE
                                 + 4 * ((lane >> 3) & 1)) * 4;

        float acc[3][3][4] = {};
        #pragma unroll
        for (int ks = 0; ks < 8; ++ks) {
            const uint32_t kbB = ks * 32;
            uint32_t a[3][4], b01[4], b2[2];
            ldsm4(a[0], qBase + qOff[0] + kbB);
            ldsm4(a[1], qBase + qOff[1] + kbB);
            ldsm4(a[2], qBase + qOff[2] + kbB);
            ldsm4(b01, kBase + kOff01 + kbB);
            ldsm2(b2,  kBase + kOff2  + kbB);
            #pragma unroll
            for (int mi = 0; mi < 3; ++mi) {
                mma_tf32(acc[mi][0], a[mi], b01);
                mma_tf32(acc[mi][1], a[mi], b01 + 2);
                mma_tf32(acc[mi][2], a[mi], b2);
            }
        }

        #pragma unroll
        for (int mi = 0; mi < 3; ++mi) {
            const int r0 = sm0 + mi * 16 + g8, r1 = r0 + 8;
            #pragma unroll
            for (int ni = 0; ni < 3; ++ni) {
                const int c0 = sn0 + ni * 8 + 2 * t4;
                *(float2*)&Ps[r0 * PS_STRIDE + c0] = *(float2*)&acc[mi][ni][0];
                *(float2*)&Ps[r1 * PS_STRIDE + c0] = *(float2*)&acc[mi][ni][2];
            }
        }
    }
    __syncthreads();

    for (int wq = warp; wq < WW; wq += 8) {
        float m = -3.4e38f;
        for (int g = lane; g < WW; g += 32) m = fmaxf(m, Ps[wq * PS_STRIDE + g]);
        #pragma unroll
        for (int o = 16; o; o >>= 1) m = fmaxf(m, __shfl_xor_sync(0xffffffffu, m, o));
        float l = 0.f;
        for (int g = lane; g < WW; g += 32) {
            uint32_t u = f2tf32(__expf(Ps[wq * PS_STRIDE + g] - m));
            Psu[wq * PS_STRIDE + g] = u;
            l += __uint_as_float(u);
        }
        #pragma unroll
        for (int o = 16; o; o >>= 1) l += __shfl_xor_sync(0xffffffffu, l, o);
        if (lane == 0) { ms[wq] = m; ls[wq] = l; }
    }
    __syncthreads();

    if (tid < WW) {
        float mh = ms[tid], lh = ls[tid];
        float mv = fv[tid], lv = fh[tid];
        float M  = fmaxf(mh, mv);
        float ev = __expf(mv - M), eh = __expf(mh - M);
        float inv = 1.f / (ev * lv + eh * lh);
        fv[tid] = ev * inv;
        fh[tid] = eh * inv;
    }

    const float gamma = *gammap;
    const int pm0 = (warp & 1) * 48, pn0 = (warp >> 1) * 32;
    uint32_t pOff[3];
    #pragma unroll
    for (int mi = 0; mi < 3; ++mi)
        pOff[mi] = ((pm0 + mi * 16 + (lane & 15)) * PS_STRIDE + 4 * (lane >> 4)) * 4;

    for (int c0 = 0; c0 < CC; c0 += 128) {
        __syncthreads();
        for (int idx = tid; idx < WW * 32; idx += 256) {
            int u0 = idx >> 5, c4 = (idx & 31) * 4;
            float4 v = *(const float4*)(g_v + (size_t)(nbase + u0) * CC + c0 + c4);
            uint4 u = { f2tf32(v.x), f2tf32(v.y), f2tf32(v.z), f2tf32(v.w) };
            *(uint4*)(Vsu + u0 * VS_STRIDE + c4) = u;
        }
        __syncthreads();

        float acc[3][4][4] = {};
        #pragma unroll
        for (int ks = 0; ks < 12; ++ks) {
            const int kb = ks * 8;
            const uint32_t kbB = ks * 32;
            uint32_t a[3][4], bf[4][2];
            ldsm4(a[0], pBase + pOff[0] + kbB);
            ldsm4(a[1], pBase + pOff[1] + kbB);
            ldsm4(a[2], pBase + pOff[2] + kbB);
            #pragma unroll
            for (int ni = 0; ni < 4; ++ni) {
                const int n = pn0 + ni * 8 + g8;
                bf[ni][0] = Vsu[(kb + t4    ) * VS_STRIDE + n];
                bf[ni][1] = Vsu[(kb + t4 + 4) * VS_STRIDE + n];
            }
            #pragma unroll
            for (int mi = 0; mi < 3; ++mi)
                #pragma unroll
                for (int ni = 0; ni < 4; ++ni)
                    mma_tf32(acc[mi][ni], a[mi], bf[ni]);
        }

        #pragma unroll
        for (int mi = 0; mi < 3; ++mi) {
            const int rA = pm0 + mi * 16 + g8;
            const int rB = rA + 8;
            const float fvA = fv[rA], fhA = fh[rA];
            const float fvB = fv[rB], fhB = fh[rB];
            const size_t oA = (size_t)(nbase + rA) * CC;
            const size_t oB = (size_t)(nbase + rB) * CC;
            #pragma unroll
            for (int ni = 0; ni < 4; ++ni) {
                const int col = c0 + pn0 + ni * 8 + 2 * t4;
                float2 avA = *(const float2*)(g_accv + oA + col);
                float2 xvA = *(const float2*)(x + oA + col);
                float2 avB = *(const float2*)(g_accv + oB + col);
                float2 xvB = *(const float2*)(x + oB + col);
                float2 o0, o1;
                o0.x = xvA.x + gamma * (fvA * avA.x + fhA * acc[mi][ni][0]);
                o0.y = xvA.y + gamma * (fvA * avA.y + fhA * acc[mi][ni][1]);
                o1.x = xvB.x + gamma * (fvB * avB.x + fhB * acc[mi][ni][2]);
                o1.y = xvB.y + gamma * (fvB * avB.y + fhB * acc[mi][ni][3]);
                *(float2*)(out + oA + col) = o0;
                *(float2*)(out + oB + col) = o1;
            }
        }
    }
}

// ---------------- launch ----------------------------------------------------
extern "C" void kernel_launch(void* const* d_in, const int* in_sizes, int n_in,
                              void* d_out, int out_size)
{
    const float* x  = (const float*)d_in[0];
    const float* Wq = (const float*)d_in[1];
    const float* bq = (const float*)d_in[2];
    const float* Wk = (const float*)d_in[3];
    const float* bk = (const float*)d_in[4];
    const float* Wv = (const float*)d_in[5];
    const float* bv = (const float*)d_in[6];
    const float* gm = (const float*)d_in[7];
    float* out = (float*)d_out;

    cudaFuncSetAttribute(col_attn, cudaFuncAttributeMaxDynamicSharedMemorySize, SMEM_BYTES);
    cudaFuncSetAttribute(row_attn, cudaFuncAttributeMaxDynamicSharedMemorySize, SMEM_BYTES);

    dim3 gA(5, 576);
    qkv_gemm<<<gA, 256>>>(x, Wq, bq, Wk, bk, Wv, bv);
    col_attn<<<768, 256, SMEM_BYTES>>>();
    row_attn<<<768, 256, SMEM_BYTES>>>(x, gm, out);
}

// round 8
// speedup vs baseline: 1.7916x; 1.1109x over previous
#include <cuda_runtime.h>
#include <cstdint>

#define HH 96
#define WW 96
#define CC 512
#define DD 64
#define N_POS 73728   // 8*96*96

// ---------------- scratch (device globals: no allocations allowed) ----------
__device__ float g_q[N_POS * DD];
__device__ float g_k[N_POS * DD];
__device__ float g_v[N_POS * CC];
__device__ float g_accv[N_POS * CC];
__device__ float g_mv[N_POS];
__device__ float g_lv[N_POS];
__device__ float g_wt[640 * 512];   // W pre-converted to tf32, n-major [n][k]

// ---------------- helpers ----------------------------------------------------
__device__ __forceinline__ uint32_t f2tf32(float f) {
    uint32_t u;
    asm("cvt.rna.tf32.f32 %0, %1;" : "=r"(u) : "f"(f));
    return u;
}

__device__ __forceinline__ void mma_tf32(float* c, const uint32_t* a, const uint32_t* b) {
    asm volatile(
        "mma.sync.aligned.m16n8k8.row.col.f32.tf32.tf32.f32 "
        "{%0,%1,%2,%3}, {%4,%5,%6,%7}, {%8,%9}, {%0,%1,%2,%3};\n"
        : "+f"(c[0]), "+f"(c[1]), "+f"(c[2]), "+f"(c[3])
        : "r"(a[0]), "r"(a[1]), "r"(a[2]), "r"(a[3]),
          "r"(b[0]), "r"(b[1]));
}

__device__ __forceinline__ uint32_t s2u(const void* p) {
    return (uint32_t)__cvta_generic_to_shared(p);
}

__device__ __forceinline__ void ldsm4(uint32_t* r, uint32_t addr) {
    asm volatile("ldmatrix.sync.aligned.m8n8.x4.shared.b16 {%0,%1,%2,%3}, [%4];"
        : "=r"(r[0]), "=r"(r[1]), "=r"(r[2]), "=r"(r[3]) : "r"(addr));
}

__device__ __forceinline__ void ldsm2(uint32_t* r, uint32_t addr) {
    asm volatile("ldmatrix.sync.aligned.m8n8.x2.shared.b16 {%0,%1}, [%2];"
        : "=r"(r[0]), "=r"(r[1]) : "r"(addr));
}

__device__ __forceinline__ void cpa16(uint32_t dst, const void* src) {
    asm volatile("cp.async.cg.shared.global [%0], [%1], 16;"
                 :: "r"(dst), "l"(src) : "memory");
}
__device__ __forceinline__ void cpa_commit() {
    asm volatile("cp.async.commit_group;" ::: "memory");
}
__device__ __forceinline__ void cpa_wait0() {
    asm volatile("cp.async.wait_group 0;" ::: "memory");
}
__device__ __forceinline__ void cpa_wait_all() {
    asm volatile("cp.async.wait_all;" ::: "memory");
}

// ---------------- Kernel 0: convert W to tf32, n-major ----------------------
// g_wt[n][k]: n 0..63 = Wq cols, 64..127 = Wk cols, 128..639 = Wv cols.
__global__ __launch_bounds__(256) void cvt_w(
    const float* __restrict__ Wq, const float* __restrict__ Wk,
    const float* __restrict__ Wv)
{
    int i = blockIdx.x * 256 + threadIdx.x;      // < 640*512
    int n = i >> 9, k = i & 511;
    float v;
    if (n < 64)       v = Wq[k * 64 + n];
    else if (n < 128) v = Wk[k * 64 + (n - 64)];
    else              v = Wv[k * 512 + (n - 128)];
    g_wt[i] = __uint_as_float(f2tf32(v));
}

// ---------------- Kernel 1: fused QKV projection GEMM (tf32 tensor) ---------
// Grid: (5, 576). ct 0 -> q|k (64+64 cols), ct 1..4 -> v cols (ct-1)*128.
// Block tile 128x128, K-chunk 32. Warps 4(M) x 2(N), warp tile 32x64.
// A: register-prefetched LDG + cvt + STS (row-major, ldmatrix).
// B: cp.async from g_wt (pre-tf32, n-major), double-buffered, 1 chunk ahead.
// smem (dynamic, uint32): As [0, 4608), Bs0 [4608, 9216), Bs1 [9216, 13824)
#define QKV_SMEM_BYTES (13824 * 4)

__global__ __launch_bounds__(256, 2) void qkv_gemm(
    const float* __restrict__ x,
    const float* __restrict__ bq, const float* __restrict__ bk,
    const float* __restrict__ bv)
{
    extern __shared__ uint32_t smQ[];
    uint32_t* As = smQ;                 // [128][36]
    // Bs stages at smQ+4608, smQ+9216 ([128][36] each)

    const int ct = blockIdx.x;
    const int rowBase = blockIdx.y * 128;
    const int ctBase = ct * 128;

    const int tid  = threadIdx.x;
    const int lane = tid & 31;
    const int warp = tid >> 5;
    const int wm   = warp >> 1;
    const int wn   = warp & 1;
    const int g8   = lane >> 2;
    const int t4   = lane & 3;

    const int arow = tid >> 3;          // 0..31
    const int acol = (tid & 7) * 4;

    const uint32_t asBase = s2u(As);
    const uint32_t bsBase = asBase + 4608 * 4;
    uint32_t aOff[2], bOff[4];
    #pragma unroll
    for (int mi = 0; mi < 2; ++mi)
        aOff[mi] = ((wm * 32 + mi * 16 + (lane & 15)) * 36 + 4 * (lane >> 4)) * 4;
    #pragma unroll
    for (int g = 0; g < 4; ++g)
        bOff[g] = ((wn * 64 + g * 16 + ((lane & 16) >> 1) + (lane & 7)) * 36
                   + 4 * ((lane >> 3) & 1)) * 4;

    // B issue: 1024 16B ops, 4 per thread
    const int bn  = (tid * 4) >> 3;          // rows covered via o = tid*4+i below
    float acc[2][8][4] = {};
    float4 pA[4];

    // prologue: B chunk 0 into stage 0; A chunk 0 into registers
    #pragma unroll
    for (int i = 0; i < 4; ++i) {
        int o = tid + i * 256;
        int n = o >> 3, seg = o & 7;
        cpa16(bsBase + (n * 36 + seg * 4) * 4,
              g_wt + (size_t)(ctBase + n) * 512 + seg * 4);
    }
    cpa_commit();
    #pragma unroll
    for (int i = 0; i < 4; ++i)
        pA[i] = *(const float4*)(x + (size_t)(rowBase + arow + i * 32) * CC + acol);

    for (int c = 0; c < 16; ++c) {
        const int s = c & 1;
        const int k0 = c * 32;

        // store A chunk c from prefetched regs
        #pragma unroll
        for (int i = 0; i < 4; ++i) {
            uint4 u = { f2tf32(pA[i].x), f2tf32(pA[i].y), f2tf32(pA[i].z), f2tf32(pA[i].w) };
            *(uint4*)&As[(arow + i * 32) * 36 + acol] = u;
        }
        cpa_wait0();            // B chunk c landed
        __syncthreads();

        if (c < 15) {
            // issue B chunk c+1 into the other stage (hidden by MMA below)
            const uint32_t bdst = bsBase + (1 - s) * 4608 * 4;
            #pragma unroll
            for (int i = 0; i < 4; ++i) {
                int o = tid + i * 256;
                int n = o >> 3, seg = o & 7;
                cpa16(bdst + (n * 36 + seg * 4) * 4,
                      g_wt + (size_t)(ctBase + n) * 512 + k0 + 32 + seg * 4);
            }
            cpa_commit();
            // prefetch A chunk c+1
            #pragma unroll
            for (int i = 0; i < 4; ++i)
                pA[i] = *(const float4*)(x + (size_t)(rowBase + arow + i * 32) * CC + k0 + 32 + acol);
        }

        const uint32_t bStage = bsBase + s * 4608 * 4;
        #pragma unroll
        for (int kk = 0; kk < 4; ++kk) {
            const uint32_t kbB = kk * 32;
            uint32_t a[2][4], bf[4][4];
            ldsm4(a[0], asBase + aOff[0] + kbB);
            ldsm4(a[1], asBase + aOff[1] + kbB);
            ldsm4(bf[0], bStage + bOff[0] + kbB);
            ldsm4(bf[1], bStage + bOff[1] + kbB);
            ldsm4(bf[2], bStage + bOff[2] + kbB);
            ldsm4(bf[3], bStage + bOff[3] + kbB);
            #pragma unroll
            for (int mi = 0; mi < 2; ++mi)
                #pragma unroll
                for (int g = 0; g < 4; ++g) {
                    mma_tf32(acc[mi][g * 2    ], a[mi], bf[g]);
                    mma_tf32(acc[mi][g * 2 + 1], a[mi], bf[g] + 2);
                }
        }
        __syncthreads();
    }

    // epilogue: bias add, rna-round, store (q/k/v consumed only as tf32)
    float* dstBase; const float* biasBase; int ldw;
    if (ct == 0) {
        if (wn == 0) { dstBase = g_q; biasBase = bq; ldw = 64; }
        else         { dstBase = g_k; biasBase = bk; ldw = 64; }
    } else {
        dstBase = g_v + (ct - 1) * 128 + wn * 64;
        biasBase = bv + (ct - 1) * 128 + wn * 64;
        ldw = CC;
    }

    #pragma unroll
    for (int ni = 0; ni < 8; ++ni) {
        const int colL = ni * 8 + 2 * t4;
        const float b0 = biasBase[colL], b1 = biasBase[colL + 1];
        #pragma unroll
        for (int mi = 0; mi < 2; ++mi) {
            const int r0 = rowBase + wm * 32 + mi * 16 + g8;
            float2 o0 = { __uint_as_float(f2tf32(acc[mi][ni][0] + b0)),
                          __uint_as_float(f2tf32(acc[mi][ni][1] + b1)) };
            float2 o1 = { __uint_as_float(f2tf32(acc[mi][ni][2] + b0)),
                          __uint_as_float(f2tf32(acc[mi][ni][3] + b1)) };
            *(float2*)(dstBase + (size_t)r0 * ldw + colL) = o0;
            *(float2*)(dstBase + (size_t)(r0 + 8) * ldw + colL) = o1;
        }
    }
}

// ---------------- shared-memory layout for attention kernels ----------------
#define QK_STRIDE 68
#define PS_STRIDE 100
#define VS_STRIDE 132
#define SM_KS   6528
#define SM_PS   13056
#define SM_MS   22656
#define SM_LS   22752
#define SM_FV   22848
#define SM_FH   22944
#define SMEM_FLOATS 23040
#define SMEM_BYTES  (SMEM_FLOATS * 4)

// ---------------- Kernel 2: column attention pass (per (b,w)) ---------------
__global__ __launch_bounds__(256, 2) void col_attn()
{
    extern __shared__ float sm[];
    uint32_t* Qs  = (uint32_t*)sm;
    uint32_t* Ks  = (uint32_t*)(sm + SM_KS);
    float*    Ps  = sm + SM_PS;
    uint32_t* Psu = (uint32_t*)Ps;
    uint32_t* Vsu = (uint32_t*)sm;   // overlays Qs+Ks

    const int tid = threadIdx.x;
    const int lane = tid & 31;
    const int warp = tid >> 5;
    const int g8 = lane >> 2, t4 = lane & 3;
    const int b = blockIdx.x / WW;
    const int w = blockIdx.x % WW;

    const uint32_t qBase = s2u(Qs), kBase = s2u(Ks), pBase = s2u(Psu), vBase = s2u(Vsu);

    // ---- load Q,K via cp.async (already tf32 bits in global) ----
    for (int idx = tid; idx < HH * 16; idx += 256) {
        int pos = idx >> 4, c4 = (idx & 15) * 4;
        size_t off = (size_t)((b * HH + pos) * WW + w) * DD + c4;
        uint32_t d = (pos * QK_STRIDE + c4) * 4;
        cpa16(qBase + d, g_q + off);
        cpa16(kBase + d, g_k + off);
    }
    cpa_wait_all();
    __syncthreads();

    // ---- scores S = Q @ K^T via tf32 MMA + ldmatrix: warps 2(M) x 4(N) ----
    {
        const int sm0 = (warp & 1) * 48, sn0 = (warp >> 1) * 24;
        uint32_t qOff[3];
        #pragma unroll
        for (int mi = 0; mi < 3; ++mi)
            qOff[mi] = ((sm0 + mi * 16 + (lane & 15)) * QK_STRIDE + 4 * (lane >> 4)) * 4;
        const uint32_t kOff01 = ((sn0 + ((lane & 16) >> 1) + (lane & 7)) * QK_STRIDE
                                 + 4 * ((lane >> 3) & 1)) * 4;
        const uint32_t kOff2  = ((sn0 + 16 + (lane & 7)) * QK_STRIDE
                                 + 4 * ((lane >> 3) & 1)) * 4;

        float acc[3][3][4] = {};
        #pragma unroll
        for (int ks = 0; ks < 8; ++ks) {
            const uint32_t kbB = ks * 32;
            uint32_t a[3][4], b01[4], b2[2];
            ldsm4(a[0], qBase + qOff[0] + kbB);
            ldsm4(a[1], qBase + qOff[1] + kbB);
            ldsm4(a[2], qBase + qOff[2] + kbB);
            ldsm4(b01, kBase + kOff01 + kbB);
            ldsm2(b2,  kBase + kOff2  + kbB);
            #pragma unroll
            for (int mi = 0; mi < 3; ++mi) {
                mma_tf32(acc[mi][0], a[mi], b01);
                mma_tf32(acc[mi][1], a[mi], b01 + 2);
                mma_tf32(acc[mi][2], a[mi], b2);
            }
        }

        #pragma unroll
        for (int mi = 0; mi < 3; ++mi) {
            const int r0 = sm0 + mi * 16 + g8, r1 = r0 + 8;
            #pragma unroll
            for (int ni = 0; ni < 3; ++ni) {
                const int c0 = sn0 + ni * 8 + 2 * t4, c1 = c0 + 1;
                Ps[r0 * PS_STRIDE + c0] = (r0 == c0) ? -1e30f : acc[mi][ni][0];
                Ps[r0 * PS_STRIDE + c1] = (r0 == c1) ? -1e30f : acc[mi][ni][1];
                Ps[r1 * PS_STRIDE + c0] = (r1 == c0) ? -1e30f : acc[mi][ni][2];
                Ps[r1 * PS_STRIDE + c1] = (r1 == c1) ? -1e30f : acc[mi][ni][3];
            }
        }
    }
    __syncthreads();

    // ---- softmax: stats + in-place convert P to tf32 bits ----
    for (int h = warp; h < HH; h += 8) {
        float m = -3.4e38f;
        for (int g = lane; g < HH; g += 32) m = fmaxf(m, Ps[h * PS_STRIDE + g]);
        #pragma unroll
        for (int o = 16; o; o >>= 1) m = fmaxf(m, __shfl_xor_sync(0xffffffffu, m, o));
        float l = 0.f;
        for (int g = lane; g < HH; g += 32) {
            uint32_t u = f2tf32(__expf(Ps[h * PS_STRIDE + g] - m));
            Psu[h * PS_STRIDE + g] = u;
            l += __uint_as_float(u);
        }
        #pragma unroll
        for (int o = 16; o; o >>= 1) l += __shfl_xor_sync(0xffffffffu, l, o);
        if (lane == 0) {
            int n = (b * HH + h) * WW + w;
            g_mv[n] = m;
            g_lv[n] = l;
        }
    }

    // ---- acc_v = P @ V: ldmatrix P (A), scalar V (B); warps 2(M) x 4(N) ----
    const int pm0 = (warp & 1) * 48, pn0 = (warp >> 1) * 32;
    uint32_t pOff[3];
    #pragma unroll
    for (int mi = 0; mi < 3; ++mi)
        pOff[mi] = ((pm0 + mi * 16 + (lane & 15)) * PS_STRIDE + 4 * (lane >> 4)) * 4;

    for (int c0 = 0; c0 < CC; c0 += 128) {
        __syncthreads();
        // fill Vs via cp.async (raw tf32 bits)
        for (int idx = tid; idx < HH * 32; idx += 256) {
            int gg = idx >> 5, c4 = (idx & 31) * 4;
            cpa16(vBase + (gg * VS_STRIDE + c4) * 4,
                  g_v + (size_t)((b * HH + gg) * WW + w) * CC + c0 + c4);
        }
        cpa_wait_all();
        __syncthreads();

        float acc[3][4][4] = {};
        #pragma unroll
        for (int ks = 0; ks < 12; ++ks) {
            const int kb = ks * 8;
            const uint32_t kbB = ks * 32;
            uint32_t a[3][4], bf[4][2];
            ldsm4(a[0], pBase + pOff[0] + kbB);
            ldsm4(a[1], pBase + pOff[1] + kbB);
            ldsm4(a[2], pBase + pOff[2] + kbB);
            #pragma unroll
            for (int ni = 0; ni < 4; ++ni) {
                const int n = pn0 + ni * 8 + g8;
                bf[ni][0] = Vsu[(kb + t4    ) * VS_STRIDE + n];
                bf[ni][1] = Vsu[(kb + t4 + 4) * VS_STRIDE + n];
            }
            #pragma unroll
            for (int mi = 0; mi < 3; ++mi)
                #pragma unroll
                for (int ni = 0; ni < 4; ++ni)
                    mma_tf32(acc[mi][ni], a[mi], bf[ni]);
        }

        #pragma unroll
        for (int mi = 0; mi < 3; ++mi) {
            const int rA = pm0 + mi * 16 + g8;
            const size_t nA = (size_t)((b * HH + rA    ) * WW + w) * CC;
            const size_t nB = (size_t)((b * HH + rA + 8) * WW + w) * CC;
            #pragma unroll
            for (int ni = 0; ni < 4; ++ni) {
                const int col = c0 + pn0 + ni * 8 + 2 * t4;
                float2 o0 = { acc[mi][ni][0], acc[mi][ni][1] };
                float2 o1 = { acc[mi][ni][2], acc[mi][ni][3] };
                *(float2*)(g_accv + nA + col) = o0;
                *(float2*)(g_accv + nB + col) = o1;
            }
        }
    }
}

// ---------------- Kernel 3: row attention pass + combine (per (b,h)) --------
__global__ __launch_bounds__(256, 2) void row_attn(
    const float* __restrict__ x, const float* __restrict__ gammap,
    float* __restrict__ out)
{
    extern __shared__ float sm[];
    uint32_t* Qs  = (uint32_t*)sm;
    uint32_t* Ks  = (uint32_t*)(sm + SM_KS);
    float*    Ps  = sm + SM_PS;
    uint32_t* Psu = (uint32_t*)Ps;
    uint32_t* Vsu = (uint32_t*)sm;
    float* ms = sm + SM_MS;
    float* ls = sm + SM_LS;
    float* fv = sm + SM_FV;
    float* fh = sm + SM_FH;

    const int tid = threadIdx.x;
    const int lane = tid & 31;
    const int warp = tid >> 5;
    const int g8 = lane >> 2, t4 = lane & 3;
    const int b = blockIdx.x / HH;
    const int h = blockIdx.x % HH;
    const int nbase = (b * HH + h) * WW;

    const uint32_t qBase = s2u(Qs), kBase = s2u(Ks), pBase = s2u(Psu), vBase = s2u(Vsu);

    for (int idx = tid; idx < WW * 16; idx += 256) {
        int pos = idx >> 4, c4 = (idx & 15) * 4;
        size_t off = (size_t)(nbase + pos) * DD + c4;
        uint32_t d = (pos * QK_STRIDE + c4) * 4;
        cpa16(qBase + d, g_q + off);
        cpa16(kBase + d, g_k + off);
    }
    if (tid < WW) {
        fv[tid] = g_mv[nbase + tid];
        fh[tid] = g_lv[nbase + tid];
    }
    cpa_wait_all();
    __syncthreads();

    // scores (no mask)
    {
        const int sm0 = (warp & 1) * 48, sn0 = (warp >> 1) * 24;
        uint32_t qOff[3];
        #pragma unroll
        for (int mi = 0; mi < 3; ++mi)
            qOff[mi] = ((sm0 + mi * 16 + (lane & 15)) * QK_STRIDE + 4 * (lane >> 4)) * 4;
        const uint32_t kOff01 = ((sn0 + ((lane & 16) >> 1) + (lane & 7)) * QK_STRIDE
                                 + 4 * ((lane >> 3) & 1)) * 4;
        const uint32_t kOff2  = ((sn0 + 16 + (lane & 7)) * QK_STRIDE
                                 + 4 * ((lane >> 3) & 1)) * 4;

        float acc[3][3][4] = {};
        #pragma unroll
        for (int ks = 0; ks < 8; ++ks) {
            const uint32_t kbB = ks * 32;
            uint32_t a[3][4], b01[4], b2[2];
            ldsm4(a[0], qBase + qOff[0] + kbB);
            ldsm4(a[1], qBase + qOff[1] + kbB);
            ldsm4(a[2], qBase + qOff[2] + kbB);
            ldsm4(b01, kBase + kOff01 + kbB);
            ldsm2(b2,  kBase + kOff2  + kbB);
            #pragma unroll
            for (int mi = 0; mi < 3; ++mi) {
                mma_tf32(acc[mi][0], a[mi], b01);
                mma_tf32(acc[mi][1], a[mi], b01 + 2);
                mma_tf32(acc[mi][2], a[mi], b2);
            }
        }

        #pragma unroll
        for (int mi = 0; mi < 3; ++mi) {
            const int r0 = sm0 + mi * 16 + g8, r1 = r0 + 8;
            #pragma unroll
            for (int ni = 0; ni < 3; ++ni) {
                const int c0 = sn0 + ni * 8 + 2 * t4;
                *(float2*)&Ps[r0 * PS_STRIDE + c0] = *(float2*)&acc[mi][ni][0];
                *(float2*)&Ps[r1 * PS_STRIDE + c0] = *(float2*)&acc[mi][ni][2];
            }
        }
    }
    __syncthreads();

    for (int wq = warp; wq < WW; wq += 8) {
        float m = -3.4e38f;
        for (int g = lane; g < WW; g += 32) m = fmaxf(m, Ps[wq * PS_STRIDE + g]);
        #pragma unroll
        for (int o = 16; o; o >>= 1) m = fmaxf(m, __shfl_xor_sync(0xffffffffu, m, o));
        float l = 0.f;
        for (int g = lane; g < WW; g += 32) {
            uint32_t u = f2tf32(__expf(Ps[wq * PS_STRIDE + g] - m));
            Psu[wq * PS_STRIDE + g] = u;
            l += __uint_as_float(u);
        }
        #pragma unroll
        for (int o = 16; o; o >>= 1) l += __shfl_xor_sync(0xffffffffu, l, o);
        if (lane == 0) { ms[wq] = m; ls[wq] = l; }
    }
    __syncthreads();

    if (tid < WW) {
        float mh = ms[tid], lh = ls[tid];
        float mv = fv[tid], lv = fh[tid];
        float M  = fmaxf(mh, mv);
        float ev = __expf(mv - M), eh = __expf(mh - M);
        float inv = 1.f / (ev * lv + eh * lh);
        fv[tid] = ev * inv;
        fh[tid] = eh * inv;
    }

    const float gamma = *gammap;
    const int pm0 = (warp & 1) * 48, pn0 = (warp >> 1) * 32;
    uint32_t pOff[3];
    #pragma unroll
    for (int mi = 0; mi < 3; ++mi)
        pOff[mi] = ((pm0 + mi * 16 + (lane & 15)) * PS_STRIDE + 4 * (lane >> 4)) * 4;

    for (int c0 = 0; c0 < CC; c0 += 128) {
        __syncthreads();
        for (int idx = tid; idx < WW * 32; idx += 256) {
            int u0 = idx >> 5, c4 = (idx & 31) * 4;
            cpa16(vBase + (u0 * VS_STRIDE + c4) * 4,
                  g_v + (size_t)(nbase + u0) * CC + c0 + c4);
        }
        cpa_wait_all();
        __syncthreads();

        float acc[3][4][4] = {};
        #pragma unroll
        for (int ks = 0; ks < 12; ++ks) {
            const int kb = ks * 8;
            const uint32_t kbB = ks * 32;
            uint32_t a[3][4], bf[4][2];
            ldsm4(a[0], pBase + pOff[0] + kbB);
            ldsm4(a[1], pBase + pOff[1] + kbB);
            ldsm4(a[2], pBase + pOff[2] + kbB);
            #pragma unroll
            for (int ni = 0; ni < 4; ++ni) {
                const int n = pn0 + ni * 8 + g8;
                bf[ni][0] = Vsu[(kb + t4    ) * VS_STRIDE + n];
                bf[ni][1] = Vsu[(kb + t4 + 4) * VS_STRIDE + n];
            }
            #pragma unroll
            for (int mi = 0; mi < 3; ++mi)
                #pragma unroll
                for (int ni = 0; ni < 4; ++ni)
                    mma_tf32(acc[mi][ni], a[mi], bf[ni]);
        }

        #pragma unroll
        for (int mi = 0; mi < 3; ++mi) {
            const int rA = pm0 + mi * 16 + g8;
            const int rB = rA + 8;
            const float fvA = fv[rA], fhA = fh[rA];
            const float fvB = fv[rB], fhB = fh[rB];
            const size_t oA = (size_t)(nbase + rA) * CC;
            const size_t oB = (size_t)(nbase + rB) * CC;
            #pragma unroll
            for (int ni = 0; ni < 4; ++ni) {
                const int col = c0 + pn0 + ni * 8 + 2 * t4;
                float2 avA = *(const float2*)(g_accv + oA + col);
                float2 xvA = *(const float2*)(x + oA + col);
                float2 avB = *(const float2*)(g_accv + oB + col);
                float2 xvB = *(const float2*)(x + oB + col);
                float2 o0, o1;
                o0.x = xvA.x + gamma * (fvA * avA.x + fhA * acc[mi][ni][0]);
                o0.y = xvA.y + gamma * (fvA * avA.y + fhA * acc[mi][ni][1]);
                o1.x = xvB.x + gamma * (fvB * avB.x + fhB * acc[mi][ni][2]);
                o1.y = xvB.y + gamma * (fvB * avB.y + fhB * acc[mi][ni][3]);
                *(float2*)(out + oA + col) = o0;
                *(float2*)(out + oB + col) = o1;
            }
        }
    }
}

// ---------------- launch ----------------------------------------------------
extern "C" void kernel_launch(void* const* d_in, const int* in_sizes, int n_in,
                              void* d_out, int out_size)
{
    const float* x  = (const float*)d_in[0];
    const float* Wq = (const float*)d_in[1];
    const float* bq = (const float*)d_in[2];
    const float* Wk = (const float*)d_in[3];
    const float* bk = (const float*)d_in[4];
    const float* Wv = (const float*)d_in[5];
    const float* bv = (const float*)d_in[6];
    const float* gm = (const float*)d_in[7];
    float* out = (float*)d_out;

    cudaFuncSetAttribute(qkv_gemm, cudaFuncAttributeMaxDynamicSharedMemorySize, QKV_SMEM_BYTES);
    cudaFuncSetAttribute(col_attn, cudaFuncAttributeMaxDynamicSharedMemorySize, SMEM_BYTES);
    cudaFuncSetAttribute(row_attn, cudaFuncAttributeMaxDynamicSharedMemorySize, SMEM_BYTES);

    cvt_w<<<1280, 256>>>(Wq, Wk, Wv);
    dim3 gA(5, 576);
    qkv_gemm<<<gA, 256, QKV_SMEM_BYTES>>>(x, bq, bk, bv);
    col_attn<<<768, 256, SMEM_BYTES>>>();
    row_attn<<<768, 256, SMEM_BYTES>>>(x, gm, out);
}

// round 9
// speedup vs baseline: 1.7970x; 1.0030x over previous
#include <cuda_runtime.h>
#include <cstdint>

#define HH 96
#define WW 96
#define CC 512
#define DD 64
#define N_POS 73728   // 8*96*96

// ---------------- scratch (device globals: no allocations allowed) ----------
__device__ float g_q[N_POS * DD];
__device__ float g_k[N_POS * DD];
__device__ float g_v[N_POS * CC];
__device__ float g_accv[N_POS * CC];
__device__ float g_mv[N_POS];
__device__ float g_lv[N_POS];
__device__ float g_wt[640 * 512];   // W pre-converted to tf32, n-major [n][k]

// ---------------- helpers ----------------------------------------------------
__device__ __forceinline__ uint32_t f2tf32(float f) {
    uint32_t u;
    asm("cvt.rna.tf32.f32 %0, %1;" : "=r"(u) : "f"(f));
    return u;
}

__device__ __forceinline__ void mma_tf32(float* c, const uint32_t* a, const uint32_t* b) {
    asm volatile(
        "mma.sync.aligned.m16n8k8.row.col.f32.tf32.tf32.f32 "
        "{%0,%1,%2,%3}, {%4,%5,%6,%7}, {%8,%9}, {%0,%1,%2,%3};\n"
        : "+f"(c[0]), "+f"(c[1]), "+f"(c[2]), "+f"(c[3])
        : "r"(a[0]), "r"(a[1]), "r"(a[2]), "r"(a[3]),
          "r"(b[0]), "r"(b[1]));
}

__device__ __forceinline__ uint32_t s2u(const void* p) {
    return (uint32_t)__cvta_generic_to_shared(p);
}

__device__ __forceinline__ void ldsm4(uint32_t* r, uint32_t addr) {
    asm volatile("ldmatrix.sync.aligned.m8n8.x4.shared.b16 {%0,%1,%2,%3}, [%4];"
        : "=r"(r[0]), "=r"(r[1]), "=r"(r[2]), "=r"(r[3]) : "r"(addr));
}

__device__ __forceinline__ void ldsm2(uint32_t* r, uint32_t addr) {
    asm volatile("ldmatrix.sync.aligned.m8n8.x2.shared.b16 {%0,%1}, [%2];"
        : "=r"(r[0]), "=r"(r[1]) : "r"(addr));
}

__device__ __forceinline__ void cpa16(uint32_t dst, const void* src) {
    asm volatile("cp.async.cg.shared.global [%0], [%1], 16;"
                 :: "r"(dst), "l"(src) : "memory");
}
__device__ __forceinline__ void cpa_commit() {
    asm volatile("cp.async.commit_group;" ::: "memory");
}
__device__ __forceinline__ void cpa_wait0() {
    asm volatile("cp.async.wait_group 0;" ::: "memory");
}
__device__ __forceinline__ void cpa_wait1() {
    asm volatile("cp.async.wait_group 1;" ::: "memory");
}
__device__ __forceinline__ void cpa_wait_all() {
    asm volatile("cp.async.wait_all;" ::: "memory");
}

// ---------------- Kernel 0: convert W to tf32, n-major ----------------------
__global__ __launch_bounds__(256) void cvt_w(
    const float* __restrict__ Wq, const float* __restrict__ Wk,
    const float* __restrict__ Wv)
{
    int i = blockIdx.x * 256 + threadIdx.x;      // < 640*512
    int n = i >> 9, k = i & 511;
    float v;
    if (n < 64)       v = Wq[k * 64 + n];
    else if (n < 128) v = Wk[k * 64 + (n - 64)];
    else              v = Wv[k * 512 + (n - 128)];
    g_wt[i] = __uint_as_float(f2tf32(v));
}

// ---------------- Kernel 1: fused QKV projection GEMM (tf32 tensor) ---------
#define QKV_SMEM_BYTES (13824 * 4)

__global__ __launch_bounds__(256, 2) void qkv_gemm(
    const float* __restrict__ x,
    const float* __restrict__ bq, const float* __restrict__ bk,
    const float* __restrict__ bv)
{
    extern __shared__ uint32_t smQ[];
    uint32_t* As = smQ;                 // [128][36]

    const int ct = blockIdx.x;
    const int rowBase = blockIdx.y * 128;
    const int ctBase = ct * 128;

    const int tid  = threadIdx.x;
    const int lane = tid & 31;
    const int warp = tid >> 5;
    const int wm   = warp >> 1;
    const int wn   = warp & 1;
    const int g8   = lane >> 2;
    const int t4   = lane & 3;

    const int arow = tid >> 3;          // 0..31
    const int acol = (tid & 7) * 4;

    const uint32_t asBase = s2u(As);
    const uint32_t bsBase = asBase + 4608 * 4;
    uint32_t aOff[2], bOff[4];
    #pragma unroll
    for (int mi = 0; mi < 2; ++mi)
        aOff[mi] = ((wm * 32 + mi * 16 + (lane & 15)) * 36 + 4 * (lane >> 4)) * 4;
    #pragma unroll
    for (int g = 0; g < 4; ++g)
        bOff[g] = ((wn * 64 + g * 16 + ((lane & 16) >> 1) + (lane & 7)) * 36
                   + 4 * ((lane >> 3) & 1)) * 4;

    float acc[2][8][4] = {};
    float4 pA[4];

    #pragma unroll
    for (int i = 0; i < 4; ++i) {
        int o = tid + i * 256;
        int n = o >> 3, seg = o & 7;
        cpa16(bsBase + (n * 36 + seg * 4) * 4,
              g_wt + (size_t)(ctBase + n) * 512 + seg * 4);
    }
    cpa_commit();
    #pragma unroll
    for (int i = 0; i < 4; ++i)
        pA[i] = *(const float4*)(x + (size_t)(rowBase + arow + i * 32) * CC + acol);

    for (int c = 0; c < 16; ++c) {
        const int s = c & 1;
        const int k0 = c * 32;

        #pragma unroll
        for (int i = 0; i < 4; ++i) {
            uint4 u = { f2tf32(pA[i].x), f2tf32(pA[i].y), f2tf32(pA[i].z), f2tf32(pA[i].w) };
            *(uint4*)&As[(arow + i * 32) * 36 + acol] = u;
        }
        cpa_wait0();
        __syncthreads();

        if (c < 15) {
            const uint32_t bdst = bsBase + (1 - s) * 4608 * 4;
            #pragma unroll
            for (int i = 0; i < 4; ++i) {
                int o = tid + i * 256;
                int n = o >> 3, seg = o & 7;
                cpa16(bdst + (n * 36 + seg * 4) * 4,
                      g_wt + (size_t)(ctBase + n) * 512 + k0 + 32 + seg * 4);
            }
            cpa_commit();
            #pragma unroll
            for (int i = 0; i < 4; ++i)
                pA[i] = *(const float4*)(x + (size_t)(rowBase + arow + i * 32) * CC + k0 + 32 + acol);
        }

        const uint32_t bStage = bsBase + s * 4608 * 4;
        #pragma unroll
        for (int kk = 0; kk < 4; ++kk) {
            const uint32_t kbB = kk * 32;
            uint32_t a[2][4], bf[4][4];
            ldsm4(a[0], asBase + aOff[0] + kbB);
            ldsm4(a[1], asBase + aOff[1] + kbB);
            ldsm4(bf[0], bStage + bOff[0] + kbB);
            ldsm4(bf[1], bStage + bOff[1] + kbB);
            ldsm4(bf[2], bStage + bOff[2] + kbB);
            ldsm4(bf[3], bStage + bOff[3] + kbB);
            #pragma unroll
            for (int mi = 0; mi < 2; ++mi)
                #pragma unroll
                for (int g = 0; g < 4; ++g) {
                    mma_tf32(acc[mi][g * 2    ], a[mi], bf[g]);
                    mma_tf32(acc[mi][g * 2 + 1], a[mi], bf[g] + 2);
                }
        }
        __syncthreads();
    }

    float* dstBase; const float* biasBase; int ldw;
    if (ct == 0) {
        if (wn == 0) { dstBase = g_q; biasBase = bq; ldw = 64; }
        else         { dstBase = g_k; biasBase = bk; ldw = 64; }
    } else {
        dstBase = g_v + (ct - 1) * 128 + wn * 64;
        biasBase = bv + (ct - 1) * 128 + wn * 64;
        ldw = CC;
    }

    #pragma unroll
    for (int ni = 0; ni < 8; ++ni) {
        const int colL = ni * 8 + 2 * t4;
        const float b0 = biasBase[colL], b1 = biasBase[colL + 1];
        #pragma unroll
        for (int mi = 0; mi < 2; ++mi) {
            const int r0 = rowBase + wm * 32 + mi * 16 + g8;
            float2 o0 = { __uint_as_float(f2tf32(acc[mi][ni][0] + b0)),
                          __uint_as_float(f2tf32(acc[mi][ni][1] + b1)) };
            float2 o1 = { __uint_as_float(f2tf32(acc[mi][ni][2] + b0)),
                          __uint_as_float(f2tf32(acc[mi][ni][3] + b1)) };
            *(float2*)(dstBase + (size_t)r0 * ldw + colL) = o0;
            *(float2*)(dstBase + (size_t)(r0 + 8) * ldw + colL) = o1;
        }
    }
}

// ---------------- shared-memory layout for attention kernels ----------------
// floats:
// [0 .. 6528)        Qs (96x68)   -- overlaid by V buf0 (96x68)
// [6528 .. 13056)    Ks (96x68)   -- overlaid by V buf1 (96x68)
// [13056 .. 22656)   Ps (96x100)  fp32 scores -> tf32 bits after softmax
// [22656 .. 23040)   stats: ms, ls, fv, fh
#define QK_STRIDE 68
#define PS_STRIDE 100
#define VCH_STRIDE 68
#define SM_KS   6528
#define SM_PS   13056
#define SM_MS   22656
#define SM_LS   22752
#define SM_FV   22848
#define SM_FH   22944
#define SMEM_FLOATS 23040
#define SMEM_BYTES  (SMEM_FLOATS * 4)
#define NCHUNK 8   // 8 chunks of 64 channels

// ---------------- Kernel 2: column attention pass (per (b,w)) ---------------
__global__ __launch_bounds__(256, 2) void col_attn()
{
    extern __shared__ float sm[];
    uint32_t* Qs  = (uint32_t*)sm;
    uint32_t* Ks  = (uint32_t*)(sm + SM_KS);
    float*    Ps  = sm + SM_PS;
    uint32_t* Psu = (uint32_t*)Ps;
    uint32_t* Vsu = (uint32_t*)sm;   // two 96x68 buffers overlay Qs|Ks

    const int tid = threadIdx.x;
    const int lane = tid & 31;
    const int warp = tid >> 5;
    const int g8 = lane >> 2, t4 = lane & 3;
    const int b = blockIdx.x / WW;
    const int w = blockIdx.x % WW;

    const uint32_t qBase = s2u(Qs), kBase = s2u(Ks), pBase = s2u(Psu), vBase = s2u(Vsu);

    // ---- load Q,K via cp.async ----
    for (int idx = tid; idx < HH * 16; idx += 256) {
        int pos = idx >> 4, c4 = (idx & 15) * 4;
        size_t off = (size_t)((b * HH + pos) * WW + w) * DD + c4;
        uint32_t d = (pos * QK_STRIDE + c4) * 4;
        cpa16(qBase + d, g_q + off);
        cpa16(kBase + d, g_k + off);
    }
    cpa_commit();
    cpa_wait_all();
    __syncthreads();

    // ---- scores S = Q @ K^T (tf32 MMA + ldmatrix), warps 2(M) x 4(N) ----
    {
        const int sm0 = (warp & 1) * 48, sn0 = (warp >> 1) * 24;
        uint32_t qOff[3];
        #pragma unroll
        for (int mi = 0; mi < 3; ++mi)
            qOff[mi] = ((sm0 + mi * 16 + (lane & 15)) * QK_STRIDE + 4 * (lane >> 4)) * 4;
        const uint32_t kOff01 = ((sn0 + ((lane & 16) >> 1) + (lane & 7)) * QK_STRIDE
                                 + 4 * ((lane >> 3) & 1)) * 4;
        const uint32_t kOff2  = ((sn0 + 16 + (lane & 7)) * QK_STRIDE
                                 + 4 * ((lane >> 3) & 1)) * 4;

        float acc[3][3][4] = {};
        #pragma unroll
        for (int ks = 0; ks < 8; ++ks) {
            const uint32_t kbB = ks * 32;
            uint32_t a[3][4], b01[4], b2[2];
            ldsm4(a[0], qBase + qOff[0] + kbB);
            ldsm4(a[1], qBase + qOff[1] + kbB);
            ldsm4(a[2], qBase + qOff[2] + kbB);
            ldsm4(b01, kBase + kOff01 + kbB);
            ldsm2(b2,  kBase + kOff2  + kbB);
            #pragma unroll
            for (int mi = 0; mi < 3; ++mi) {
                mma_tf32(acc[mi][0], a[mi], b01);
                mma_tf32(acc[mi][1], a[mi], b01 + 2);
                mma_tf32(acc[mi][2], a[mi], b2);
            }
        }

        #pragma unroll
        for (int mi = 0; mi < 3; ++mi) {
            const int r0 = sm0 + mi * 16 + g8, r1 = r0 + 8;
            #pragma unroll
            for (int ni = 0; ni < 3; ++ni) {
                const int c0 = sn0 + ni * 8 + 2 * t4, c1 = c0 + 1;
                Ps[r0 * PS_STRIDE + c0] = (r0 == c0) ? -1e30f : acc[mi][ni][0];
                Ps[r0 * PS_STRIDE + c1] = (r0 == c1) ? -1e30f : acc[mi][ni][1];
                Ps[r1 * PS_STRIDE + c0] = (r1 == c0) ? -1e30f : acc[mi][ni][2];
                Ps[r1 * PS_STRIDE + c1] = (r1 == c1) ? -1e30f : acc[mi][ni][3];
            }
        }
    }
    __syncthreads();   // Qs/Ks now dead

    // issue V chunk 0 (overlaps softmax)
    {
        const uint32_t dst = vBase;
        for (int idx = tid; idx < HH * 16; idx += 256) {
            int gg = idx >> 4, c4 = (idx & 15) * 4;
            cpa16(dst + (gg * VCH_STRIDE + c4) * 4,
                  g_v + (size_t)((b * HH + gg) * WW + w) * CC + c4);
        }
        cpa_commit();
    }

    // ---- softmax ----
    for (int h = warp; h < HH; h += 8) {
        float m = -3.4e38f;
        for (int g = lane; g < HH; g += 32) m = fmaxf(m, Ps[h * PS_STRIDE + g]);
        #pragma unroll
        for (int o = 16; o; o >>= 1) m = fmaxf(m, __shfl_xor_sync(0xffffffffu, m, o));
        float l = 0.f;
        for (int g = lane; g < HH; g += 32) {
            uint32_t u = f2tf32(__expf(Ps[h * PS_STRIDE + g] - m));
            Psu[h * PS_STRIDE + g] = u;
            l += __uint_as_float(u);
        }
        #pragma unroll
        for (int o = 16; o; o >>= 1) l += __shfl_xor_sync(0xffffffffu, l, o);
        if (lane == 0) {
            int n = (b * HH + h) * WW + w;
            g_mv[n] = m;
            g_lv[n] = l;
        }
    }

    // ---- acc_v = P @ V, pipelined 64-wide chunks ----
    const int pm0 = (warp & 1) * 48, pn0 = (warp >> 1) * 16;
    uint32_t pOff[3];
    #pragma unroll
    for (int mi = 0; mi < 3; ++mi)
        pOff[mi] = ((pm0 + mi * 16 + (lane & 15)) * PS_STRIDE + 4 * (lane >> 4)) * 4;

    for (int c = 0; c < NCHUNK; ++c) {
        if (c + 1 < NCHUNK) {
            const uint32_t dst = vBase + ((c + 1) & 1) * 6528 * 4;
            for (int idx = tid; idx < HH * 16; idx += 256) {
                int gg = idx >> 4, c4 = (idx & 15) * 4;
                cpa16(dst + (gg * VCH_STRIDE + c4) * 4,
                      g_v + (size_t)((b * HH + gg) * WW + w) * CC + (c + 1) * 64 + c4);
            }
            cpa_commit();
            cpa_wait1();
        } else {
            cpa_wait0();
        }
        __syncthreads();

        const uint32_t* Vb = Vsu + (c & 1) * 6528;
        float acc[3][2][4] = {};
        #pragma unroll
        for (int ks = 0; ks < 12; ++ks) {
            const int kb = ks * 8;
            const uint32_t kbB = ks * 32;
            uint32_t a[3][4], bf[2][2];
            ldsm4(a[0], pBase + pOff[0] + kbB);
            ldsm4(a[1], pBase + pOff[1] + kbB);
            ldsm4(a[2], pBase + pOff[2] + kbB);
            #pragma unroll
            for (int ni = 0; ni < 2; ++ni) {
                const int n = pn0 + ni * 8 + g8;
                bf[ni][0] = Vb[(kb + t4    ) * VCH_STRIDE + n];
                bf[ni][1] = Vb[(kb + t4 + 4) * VCH_STRIDE + n];
            }
            #pragma unroll
            for (int mi = 0; mi < 3; ++mi)
                #pragma unroll
                for (int ni = 0; ni < 2; ++ni)
                    mma_tf32(acc[mi][ni], a[mi], bf[ni]);
        }

        #pragma unroll
        for (int mi = 0; mi < 3; ++mi) {
            const int rA = pm0 + mi * 16 + g8;
            const size_t nA = (size_t)((b * HH + rA    ) * WW + w) * CC;
            const size_t nB = (size_t)((b * HH + rA + 8) * WW + w) * CC;
            #pragma unroll
            for (int ni = 0; ni < 2; ++ni) {
                const int col = c * 64 + pn0 + ni * 8 + 2 * t4;
                float2 o0 = { acc[mi][ni][0], acc[mi][ni][1] };
                float2 o1 = { acc[mi][ni][2], acc[mi][ni][3] };
                *(float2*)(g_accv + nA + col) = o0;
                *(float2*)(g_accv + nB + col) = o1;
            }
        }
        __syncthreads();
    }
}

// ---------------- Kernel 3: row attention pass + combine (per (b,h)) --------
__global__ __launch_bounds__(256, 2) void row_attn(
    const float* __restrict__ x, const float* __restrict__ gammap,
    float* __restrict__ out)
{
    extern __shared__ float sm[];
    uint32_t* Qs  = (uint32_t*)sm;
    uint32_t* Ks  = (uint32_t*)(sm + SM_KS);
    float*    Ps  = sm + SM_PS;
    uint32_t* Psu = (uint32_t*)Ps;
    uint32_t* Vsu = (uint32_t*)sm;
    float* ms = sm + SM_MS;
    float* ls = sm + SM_LS;
    float* fv = sm + SM_FV;
    float* fh = sm + SM_FH;

    const int tid = threadIdx.x;
    const int lane = tid & 31;
    const int warp = tid >> 5;
    const int g8 = lane >> 2, t4 = lane & 3;
    const int b = blockIdx.x / HH;
    const int h = blockIdx.x % HH;
    const int nbase = (b * HH + h) * WW;

    const uint32_t qBase = s2u(Qs), kBase = s2u(Ks), pBase = s2u(Psu), vBase = s2u(Vsu);

    for (int idx = tid; idx < WW * 16; idx += 256) {
        int pos = idx >> 4, c4 = (idx & 15) * 4;
        size_t off = (size_t)(nbase + pos) * DD + c4;
        uint32_t d = (pos * QK_STRIDE + c4) * 4;
        cpa16(qBase + d, g_q + off);
        cpa16(kBase + d, g_k + off);
    }
    if (tid < WW) {
        fv[tid] = g_mv[nbase + tid];
        fh[tid] = g_lv[nbase + tid];
    }
    cpa_commit();
    cpa_wait_all();
    __syncthreads();

    // scores (no mask)
    {
        const int sm0 = (warp & 1) * 48, sn0 = (warp >> 1) * 24;
        uint32_t qOff[3];
        #pragma unroll
        for (int mi = 0; mi < 3; ++mi)
            qOff[mi] = ((sm0 + mi * 16 + (lane & 15)) * QK_STRIDE + 4 * (lane >> 4)) * 4;
        const uint32_t kOff01 = ((sn0 + ((lane & 16) >> 1) + (lane & 7)) * QK_STRIDE
                                 + 4 * ((lane >> 3) & 1)) * 4;
        const uint32_t kOff2  = ((sn0 + 16 + (lane & 7)) * QK_STRIDE
                                 + 4 * ((lane >> 3) & 1)) * 4;

        float acc[3][3][4] = {};
        #pragma unroll
        for (int ks = 0; ks < 8; ++ks) {
            const uint32_t kbB = ks * 32;
            uint32_t a[3][4], b01[4], b2[2];
            ldsm4(a[0], qBase + qOff[0] + kbB);
            ldsm4(a[1], qBase + qOff[1] + kbB);
            ldsm4(a[2], qBase + qOff[2] + kbB);
            ldsm4(b01, kBase + kOff01 + kbB);
            ldsm2(b2,  kBase + kOff2  + kbB);
            #pragma unroll
            for (int mi = 0; mi < 3; ++mi) {
                mma_tf32(acc[mi][0], a[mi], b01);
                mma_tf32(acc[mi][1], a[mi], b01 + 2);
                mma_tf32(acc[mi][2], a[mi], b2);
            }
        }

        #pragma unroll
        for (int mi = 0; mi < 3; ++mi) {
            const int r0 = sm0 + mi * 16 + g8, r1 = r0 + 8;
            #pragma unroll
            for (int ni = 0; ni < 3; ++ni) {
                const int c0 = sn0 + ni * 8 + 2 * t4;
                *(float2*)&Ps[r0 * PS_STRIDE + c0] = *(float2*)&acc[mi][ni][0];
                *(float2*)&Ps[r1 * PS_STRIDE + c0] = *(float2*)&acc[mi][ni][2];
            }
        }
    }
    __syncthreads();   // Qs/Ks dead

    // issue V chunk 0 (overlaps softmax)
    {
        for (int idx = tid; idx < WW * 16; idx += 256) {
            int u0 = idx >> 4, c4 = (idx & 15) * 4;
            cpa16(vBase + (u0 * VCH_STRIDE + c4) * 4,
                  g_v + (size_t)(nbase + u0) * CC + c4);
        }
        cpa_commit();
    }

    for (int wq = warp; wq < WW; wq += 8) {
        float m = -3.4e38f;
        for (int g = lane; g < WW; g += 32) m = fmaxf(m, Ps[wq * PS_STRIDE + g]);
        #pragma unroll
        for (int o = 16; o; o >>= 1) m = fmaxf(m, __shfl_xor_sync(0xffffffffu, m, o));
        float l = 0.f;
        for (int g = lane; g < WW; g += 32) {
            uint32_t u = f2tf32(__expf(Ps[wq * PS_STRIDE + g] - m));
            Psu[wq * PS_STRIDE + g] = u;
            l += __uint_as_float(u);
        }
        #pragma unroll
        for (int o = 16; o; o >>= 1) l += __shfl_xor_sync(0xffffffffu, l, o);
        if (lane == 0) { ms[wq] = m; ls[wq] = l; }
    }
    __syncthreads();

    if (tid < WW) {
        float mh = ms[tid], lh = ls[tid];
        float mv = fv[tid], lv = fh[tid];
        float M  = fmaxf(mh, mv);
        float ev = __expf(mv - M), eh = __expf(mh - M);
        float inv = 1.f / (ev * lv + eh * lh);
        fv[tid] = ev * inv;
        fh[tid] = eh * inv;
    }

    const float gamma = *gammap;
    const int pm0 = (warp & 1) * 48, pn0 = (warp >> 1) * 16;
    uint32_t pOff[3];
    #pragma unroll
    for (int mi = 0; mi < 3; ++mi)
        pOff[mi] = ((pm0 + mi * 16 + (lane & 15)) * PS_STRIDE + 4 * (lane >> 4)) * 4;

    for (int c = 0; c < NCHUNK; ++c) {
        if (c + 1 < NCHUNK) {
            const uint32_t dst = vBase + ((c + 1) & 1) * 6528 * 4;
            for (int idx = tid; idx < WW * 16; idx += 256) {
                int u0 = idx >> 4, c4 = (idx & 15) * 4;
                cpa16(dst + (u0 * VCH_STRIDE + c4) * 4,
                      g_v + (size_t)(nbase + u0) * CC + (c + 1) * 64 + c4);
            }
            cpa_commit();
            cpa_wait1();
        } else {
            cpa_wait0();
        }
        __syncthreads();

        // prefetch epilogue operands (accv, x) into registers
        float2 pav[3][2][2], pxv[3][2][2];
        #pragma unroll
        for (int mi = 0; mi < 3; ++mi) {
            const int rA = pm0 + mi * 16 + g8;
            const size_t oA = (size_t)(nbase + rA) * CC;
            const size_t oB = (size_t)(nbase + rA + 8) * CC;
            #pragma unroll
            for (int ni = 0; ni < 2; ++ni) {
                const int col = c * 64 + pn0 + ni * 8 + 2 * t4;
                pav[mi][ni][0] = *(const float2*)(g_accv + oA + col);
                pxv[mi][ni][0] = *(const float2*)(x + oA + col);
                pav[mi][ni][1] = *(const float2*)(g_accv + oB + col);
                pxv[mi][ni][1] = *(const float2*)(x + oB + col);
            }
        }

        const uint32_t* Vb = Vsu + (c & 1) * 6528;
        float acc[3][2][4] = {};
        #pragma unroll
        for (int ks = 0; ks < 12; ++ks) {
            const int kb = ks * 8;
            const uint32_t kbB = ks * 32;
            uint32_t a[3][4], bf[2][2];
            ldsm4(a[0], pBase + pOff[0] + kbB);
            ldsm4(a[1], pBase + pOff[1] + kbB);
            ldsm4(a[2], pBase + pOff[2] + kbB);
            #pragma unroll
            for (int ni = 0; ni < 2; ++ni) {
                const int n = pn0 + ni * 8 + g8;
                bf[ni][0] = Vb[(kb + t4    ) * VCH_STRIDE + n];
                bf[ni][1] = Vb[(kb + t4 + 4) * VCH_STRIDE + n];
            }
            #pragma unroll
            for (int mi = 0; mi < 3; ++mi)
                #pragma unroll
                for (int ni = 0; ni < 2; ++ni)
                    mma_tf32(acc[mi][ni], a[mi], bf[ni]);
        }

        #pragma unroll
        for (int mi = 0; mi < 3; ++mi) {
            const int rA = pm0 + mi * 16 + g8;
            const int rB = rA + 8;
            const float fvA = fv[rA], fhA = fh[rA];
            const float fvB = fv[rB], fhB = fh[rB];
            const size_t oA = (size_t)(nbase + rA) * CC;
            const size_t oB = (size_t)(nbase + rB) * CC;
            #pragma unroll
            for (int ni = 0; ni < 2; ++ni) {
                const int col = c * 64 + pn0 + ni * 8 + 2 * t4;
                float2 o0, o1;
                o0.x = pxv[mi][ni][0].x + gamma * (fvA * pav[mi][ni][0].x + fhA * acc[mi][ni][0]);
                o0.y = pxv[mi][ni][0].y + gamma * (fvA * pav[mi][ni][0].y + fhA * acc[mi][ni][1]);
                o1.x = pxv[mi][ni][1].x + gamma * (fvB * pav[mi][ni][1].x + fhB * acc[mi][ni][2]);
                o1.y = pxv[mi][ni][1].y + gamma * (fvB * pav[mi][ni][1].y + fhB * acc[mi][ni][3]);
                *(float2*)(out + oA + col) = o0;
                *(float2*)(out + oB + col) = o1;
            }
        }
        __syncthreads();
    }
}

// ---------------- launch ----------------------------------------------------
extern "C" void kernel_launch(void* const* d_in, const int* in_sizes, int n_in,
                              void* d_out, int out_size)
{
    const float* x  = (const float*)d_in[0];
    const float* Wq = (const float*)d_in[1];
    const float* bq = (const float*)d_in[2];
    const float* Wk = (const float*)d_in[3];
    const float* bk = (const float*)d_in[4];
    const float* Wv = (const float*)d_in[5];
    const float* bv = (const float*)d_in[6];
    const float* gm = (const float*)d_in[7];
    float* out = (float*)d_out;

    cudaFuncSetAttribute(qkv_gemm, cudaFuncAttributeMaxDynamicSharedMemorySize, QKV_SMEM_BYTES);
    cudaFuncSetAttribute(col_attn, cudaFuncAttributeMaxDynamicSharedMemorySize, SMEM_BYTES);
    cudaFuncSetAttribute(row_attn, cudaFuncAttributeMaxDynamicSharedMemorySize, SMEM_BYTES);

    cvt_w<<<1280, 256>>>(Wq, Wk, Wv);
    dim3 gA(5, 576);
    qkv_gemm<<<gA, 256, QKV_SMEM_BYTES>>>(x, bq, bk, bv);
    col_attn<<<768, 256, SMEM_BYTES>>>();
    row_attn<<<768, 256, SMEM_BYTES>>>(x, gm, out);
}

// round 10
// speedup vs baseline: 1.8162x; 1.0107x over previous
#include <cuda_runtime.h>
#include <cstdint>

#define HH 96
#define WW 96
#define CC 512
#define DD 64
#define N_POS 73728   // 8*96*96

// ---------------- scratch (device globals: no allocations allowed) ----------
__device__ float g_q[N_POS * DD];
__device__ float g_k[N_POS * DD];
__device__ float g_v[N_POS * CC];
__device__ float g_accv[N_POS * CC];
__device__ float g_mv[N_POS];
__device__ float g_lv[N_POS];
__device__ float g_wt[640 * 512];   // W pre-converted to tf32 (rna), n-major [n][k]

// ---------------- helpers ----------------------------------------------------
__device__ __forceinline__ uint32_t f2tf32(float f) {
    uint32_t u;
    asm("cvt.rna.tf32.f32 %0, %1;" : "=r"(u) : "f"(f));
    return u;
}

__device__ __forceinline__ void mma_tf32(float* c, const uint32_t* a, const uint32_t* b) {
    asm volatile(
        "mma.sync.aligned.m16n8k8.row.col.f32.tf32.tf32.f32 "
        "{%0,%1,%2,%3}, {%4,%5,%6,%7}, {%8,%9}, {%0,%1,%2,%3};\n"
        : "+f"(c[0]), "+f"(c[1]), "+f"(c[2]), "+f"(c[3])
        : "r"(a[0]), "r"(a[1]), "r"(a[2]), "r"(a[3]),
          "r"(b[0]), "r"(b[1]));
}

__device__ __forceinline__ uint32_t s2u(const void* p) {
    return (uint32_t)__cvta_generic_to_shared(p);
}

__device__ __forceinline__ void ldsm4(uint32_t* r, uint32_t addr) {
    asm volatile("ldmatrix.sync.aligned.m8n8.x4.shared.b16 {%0,%1,%2,%3}, [%4];"
        : "=r"(r[0]), "=r"(r[1]), "=r"(r[2]), "=r"(r[3]) : "r"(addr));
}

__device__ __forceinline__ void ldsm2(uint32_t* r, uint32_t addr) {
    asm volatile("ldmatrix.sync.aligned.m8n8.x2.shared.b16 {%0,%1}, [%2];"
        : "=r"(r[0]), "=r"(r[1]) : "r"(addr));
}

__device__ __forceinline__ void cpa16(uint32_t dst, const void* src) {
    asm volatile("cp.async.cg.shared.global [%0], [%1], 16;"
                 :: "r"(dst), "l"(src) : "memory");
}
__device__ __forceinline__ void cpa_commit() {
    asm volatile("cp.async.commit_group;" ::: "memory");
}
__device__ __forceinline__ void cpa_wait0() {
    asm volatile("cp.async.wait_group 0;" ::: "memory");
}
__device__ __forceinline__ void cpa_wait1() {
    asm volatile("cp.async.wait_group 1;" ::: "memory");
}
__device__ __forceinline__ void cpa_wait_all() {
    asm volatile("cp.async.wait_all;" ::: "memory");
}

// ---------------- Kernel 0: convert W to tf32, n-major ----------------------
__global__ __launch_bounds__(256) void cvt_w(
    const float* __restrict__ Wq, const float* __restrict__ Wk,
    const float* __restrict__ Wv)
{
    int i = blockIdx.x * 256 + threadIdx.x;      // < 640*512
    int n = i >> 9, k = i & 511;
    float v;
    if (n < 64)       v = Wq[k * 64 + n];
    else if (n < 128) v = Wk[k * 64 + (n - 64)];
    else              v = Wv[k * 512 + (n - 128)];
    g_wt[i] = __uint_as_float(f2tf32(v));
}

// ---------------- Kernel 1: fused QKV projection GEMM (tf32 tensor) ---------
// Grid: (5, 576). ct 0 -> q|k (64+64 cols), ct 1..4 -> v cols (ct-1)*128.
// Block tile 128x128, K-chunk 32. Warps 4(M) x 2(N), warp tile 32x64.
// Fully asynchronous: A = raw fp32 x via cp.async (tf32 MMA truncates),
// B = pre-rna tf32 from g_wt via cp.async. 3-stage pipeline, depth 2.
// smem (u32): stage s at s*9216: A [0,4608), B [4608,9216). 110592 bytes.
#define QKV_SMEM_BYTES (3 * 9216 * 4)

__global__ __launch_bounds__(256, 2) void qkv_gemm(
    const float* __restrict__ x,
    const float* __restrict__ bq, const float* __restrict__ bk,
    const float* __restrict__ bv)
{
    extern __shared__ uint32_t smQ[];

    const int ct = blockIdx.x;
    const int rowBase = blockIdx.y * 128;
    const int ctBase = ct * 128;

    const int tid  = threadIdx.x;
    const int lane = tid & 31;
    const int warp = tid >> 5;
    const int wm   = warp >> 1;
    const int wn   = warp & 1;
    const int g8   = lane >> 2;
    const int t4   = lane & 3;

    const uint32_t smBase = s2u(smQ);
    uint32_t aOff[2], bOff[4];
    #pragma unroll
    for (int mi = 0; mi < 2; ++mi)
        aOff[mi] = ((wm * 32 + mi * 16 + (lane & 15)) * 36 + 4 * (lane >> 4)) * 4;
    #pragma unroll
    for (int g = 0; g < 4; ++g)
        bOff[g] = (4608 + (wn * 64 + g * 16 + ((lane & 16) >> 1) + (lane & 7)) * 36
                   + 4 * ((lane >> 3) & 1)) * 4;

    // per-thread fill coordinates: 4 segments each for A and B
    const int frow = tid >> 1;                 // 0..127 (2 threads/row)
    const int fs0  = (tid & 1) * 4;            // first seg of this thread's 4
    // Each thread does rows? Simpler: idx scheme (tid + i*256): row=idx>>3, seg=idx&7.

    float acc[2][8][4] = {};
    (void)frow; (void)fs0;

    // ---- issue chunk helper (A raw x, B from g_wt) ----
    auto issue_chunk = [&](int c, int s) {
        const uint32_t aDst = smBase + (s * 9216) * 4;
        const uint32_t bDst = smBase + (s * 9216 + 4608) * 4;
        const int k0 = c * 32;
        #pragma unroll
        for (int i = 0; i < 4; ++i) {
            int idx = tid + i * 256;           // 0..1023
            int row = idx >> 3, seg = idx & 7;
            cpa16(aDst + (row * 36 + seg * 4) * 4,
                  x + (size_t)(rowBase + row) * CC + k0 + seg * 4);
        }
        #pragma unroll
        for (int i = 0; i < 4; ++i) {
            int idx = tid + i * 256;
            int row = idx >> 3, seg = idx & 7;
            cpa16(bDst + (row * 36 + seg * 4) * 4,
                  g_wt + (size_t)(ctBase + row) * 512 + k0 + seg * 4);
        }
        cpa_commit();
    };

    issue_chunk(0, 0);
    issue_chunk(1, 1);

    for (int c = 0; c < 16; ++c) {
        const int s = c % 3;
        cpa_wait1();          // chunk c landed (chunk c+1 may be in flight)
        __syncthreads();      // all warps done with stage (c-1)%3 == (c+2)%3 reads

        if (c + 2 < 16) issue_chunk(c + 2, (c + 2) % 3);

        const uint32_t aStage = smBase + (s * 9216) * 4;
        #pragma unroll
        for (int kk = 0; kk < 4; ++kk) {
            const uint32_t kbB = kk * 32;
            uint32_t a[2][4], bf[4][4];
            ldsm4(a[0], aStage + aOff[0] + kbB);
            ldsm4(a[1], aStage + aOff[1] + kbB);
            ldsm4(bf[0], aStage + bOff[0] + kbB);
            ldsm4(bf[1], aStage + bOff[1] + kbB);
            ldsm4(bf[2], aStage + bOff[2] + kbB);
            ldsm4(bf[3], aStage + bOff[3] + kbB);
            #pragma unroll
            for (int mi = 0; mi < 2; ++mi)
                #pragma unroll
                for (int g = 0; g < 4; ++g) {
                    mma_tf32(acc[mi][g * 2    ], a[mi], bf[g]);
                    mma_tf32(acc[mi][g * 2 + 1], a[mi], bf[g] + 2);
                }
        }
    }

    float* dstBase; const float* biasBase; int ldw;
    if (ct == 0) {
        if (wn == 0) { dstBase = g_q; biasBase = bq; ldw = 64; }
        else         { dstBase = g_k; biasBase = bk; ldw = 64; }
    } else {
        dstBase = g_v + (ct - 1) * 128 + wn * 64;
        biasBase = bv + (ct - 1) * 128 + wn * 64;
        ldw = CC;
    }

    #pragma unroll
    for (int ni = 0; ni < 8; ++ni) {
        const int colL = ni * 8 + 2 * t4;
        const float b0 = biasBase[colL], b1 = biasBase[colL + 1];
        #pragma unroll
        for (int mi = 0; mi < 2; ++mi) {
            const int r0 = rowBase + wm * 32 + mi * 16 + g8;
            float2 o0 = { __uint_as_float(f2tf32(acc[mi][ni][0] + b0)),
                          __uint_as_float(f2tf32(acc[mi][ni][1] + b1)) };
            float2 o1 = { __uint_as_float(f2tf32(acc[mi][ni][2] + b0)),
                          __uint_as_float(f2tf32(acc[mi][ni][3] + b1)) };
            *(float2*)(dstBase + (size_t)r0 * ldw + colL) = o0;
            *(float2*)(dstBase + (size_t)(r0 + 8) * ldw + colL) = o1;
        }
    }
}

// ---------------- shared-memory layout for attention kernels ----------------
#define QK_STRIDE 68
#define PS_STRIDE 100
#define VCH_STRIDE 68
#define SM_KS   6528
#define SM_PS   13056
#define SM_MS   22656
#define SM_LS   22752
#define SM_FV   22848
#define SM_FH   22944
#define SMEM_FLOATS 23040
#define SMEM_BYTES  (SMEM_FLOATS * 4)
#define NCHUNK 8   // 8 chunks of 64 channels

// ---------------- Kernel 2: column attention pass (per (b,w)) ---------------
__global__ __launch_bounds__(256, 2) void col_attn()
{
    extern __shared__ float sm[];
    uint32_t* Qs  = (uint32_t*)sm;
    uint32_t* Ks  = (uint32_t*)(sm + SM_KS);
    float*    Ps  = sm + SM_PS;
    uint32_t* Psu = (uint32_t*)Ps;
    uint32_t* Vsu = (uint32_t*)sm;   // two 96x68 buffers overlay Qs|Ks

    const int tid = threadIdx.x;
    const int lane = tid & 31;
    const int warp = tid >> 5;
    const int g8 = lane >> 2, t4 = lane & 3;
    const int b = blockIdx.x / WW;
    const int w = blockIdx.x % WW;

    const uint32_t qBase = s2u(Qs), kBase = s2u(Ks), pBase = s2u(Psu), vBase = s2u(Vsu);

    for (int idx = tid; idx < HH * 16; idx += 256) {
        int pos = idx >> 4, c4 = (idx & 15) * 4;
        size_t off = (size_t)((b * HH + pos) * WW + w) * DD + c4;
        uint32_t d = (pos * QK_STRIDE + c4) * 4;
        cpa16(qBase + d, g_q + off);
        cpa16(kBase + d, g_k + off);
    }
    cpa_commit();
    cpa_wait_all();
    __syncthreads();

    {
        const int sm0 = (warp & 1) * 48, sn0 = (warp >> 1) * 24;
        uint32_t qOff[3];
        #pragma unroll
        for (int mi = 0; mi < 3; ++mi)
            qOff[mi] = ((sm0 + mi * 16 + (lane & 15)) * QK_STRIDE + 4 * (lane >> 4)) * 4;
        const uint32_t kOff01 = ((sn0 + ((lane & 16) >> 1) + (lane & 7)) * QK_STRIDE
                                 + 4 * ((lane >> 3) & 1)) * 4;
        const uint32_t kOff2  = ((sn0 + 16 + (lane & 7)) * QK_STRIDE
                                 + 4 * ((lane >> 3) & 1)) * 4;

        float acc[3][3][4] = {};
        #pragma unroll
        for (int ks = 0; ks < 8; ++ks) {
            const uint32_t kbB = ks * 32;
            uint32_t a[3][4], b01[4], b2[2];
            ldsm4(a[0], qBase + qOff[0] + kbB);
            ldsm4(a[1], qBase + qOff[1] + kbB);
            ldsm4(a[2], qBase + qOff[2] + kbB);
            ldsm4(b01, kBase + kOff01 + kbB);
            ldsm2(b2,  kBase + kOff2  + kbB);
            #pragma unroll
            for (int mi = 0; mi < 3; ++mi) {
                mma_tf32(acc[mi][0], a[mi], b01);
                mma_tf32(acc[mi][1], a[mi], b01 + 2);
                mma_tf32(acc[mi][2], a[mi], b2);
            }
        }

        #pragma unroll
        for (int mi = 0; mi < 3; ++mi) {
            const int r0 = sm0 + mi * 16 + g8, r1 = r0 + 8;
            #pragma unroll
            for (int ni = 0; ni < 3; ++ni) {
                const int c0 = sn0 + ni * 8 + 2 * t4, c1 = c0 + 1;
                Ps[r0 * PS_STRIDE + c0] = (r0 == c0) ? -1e30f : acc[mi][ni][0];
                Ps[r0 * PS_STRIDE + c1] = (r0 == c1) ? -1e30f : acc[mi][ni][1];
                Ps[r1 * PS_STRIDE + c0] = (r1 == c0) ? -1e30f : acc[mi][ni][2];
                Ps[r1 * PS_STRIDE + c1] = (r1 == c1) ? -1e30f : acc[mi][ni][3];
            }
        }
    }
    __syncthreads();   // Qs/Ks now dead

    {
        const uint32_t dst = vBase;
        for (int idx = tid; idx < HH * 16; idx += 256) {
            int gg = idx >> 4, c4 = (idx & 15) * 4;
            cpa16(dst + (gg * VCH_STRIDE + c4) * 4,
                  g_v + (size_t)((b * HH + gg) * WW + w) * CC + c4);
        }
        cpa_commit();
    }

    for (int h = warp; h < HH; h += 8) {
        float m = -3.4e38f;
        for (int g = lane; g < HH; g += 32) m = fmaxf(m, Ps[h * PS_STRIDE + g]);
        #pragma unroll
        for (int o = 16; o; o >>= 1) m = fmaxf(m, __shfl_xor_sync(0xffffffffu, m, o));
        float l = 0.f;
        for (int g = lane; g < HH; g += 32) {
            uint32_t u = f2tf32(__expf(Ps[h * PS_STRIDE + g] - m));
            Psu[h * PS_STRIDE + g] = u;
            l += __uint_as_float(u);
        }
        #pragma unroll
        for (int o = 16; o; o >>= 1) l += __shfl_xor_sync(0xffffffffu, l, o);
        if (lane == 0) {
            int n = (b * HH + h) * WW + w;
            g_mv[n] = m;
            g_lv[n] = l;
        }
    }

    const int pm0 = (warp & 1) * 48, pn0 = (warp >> 1) * 16;
    uint32_t pOff[3];
    #pragma unroll
    for (int mi = 0; mi < 3; ++mi)
        pOff[mi] = ((pm0 + mi * 16 + (lane & 15)) * PS_STRIDE + 4 * (lane >> 4)) * 4;

    for (int c = 0; c < NCHUNK; ++c) {
        if (c + 1 < NCHUNK) {
            const uint32_t dst = vBase + ((c + 1) & 1) * 6528 * 4;
            for (int idx = tid; idx < HH * 16; idx += 256) {
                int gg = idx >> 4, c4 = (idx & 15) * 4;
                cpa16(dst + (gg * VCH_STRIDE + c4) * 4,
                      g_v + (size_t)((b * HH + gg) * WW + w) * CC + (c + 1) * 64 + c4);
            }
            cpa_commit();
            cpa_wait1();
        } else {
            cpa_wait0();
        }
        __syncthreads();

        const uint32_t* Vb = Vsu + (c & 1) * 6528;
        float acc[3][2][4] = {};
        #pragma unroll
        for (int ks = 0; ks < 12; ++ks) {
            const int kb = ks * 8;
            const uint32_t kbB = ks * 32;
            uint32_t a[3][4], bf[2][2];
            ldsm4(a[0], pBase + pOff[0] + kbB);
            ldsm4(a[1], pBase + pOff[1] + kbB);
            ldsm4(a[2], pBase + pOff[2] + kbB);
            #pragma unroll
            for (int ni = 0; ni < 2; ++ni) {
                const int n = pn0 + ni * 8 + g8;
                bf[ni][0] = Vb[(kb + t4    ) * VCH_STRIDE + n];
                bf[ni][1] = Vb[(kb + t4 + 4) * VCH_STRIDE + n];
            }
            #pragma unroll
            for (int mi = 0; mi < 3; ++mi)
                #pragma unroll
                for (int ni = 0; ni < 2; ++ni)
                    mma_tf32(acc[mi][ni], a[mi], bf[ni]);
        }

        #pragma unroll
        for (int mi = 0; mi < 3; ++mi) {
            const int rA = pm0 + mi * 16 + g8;
            const size_t nA = (size_t)((b * HH + rA    ) * WW + w) * CC;
            const size_t nB = (size_t)((b * HH + rA + 8) * WW + w) * CC;
            #pragma unroll
            for (int ni = 0; ni < 2; ++ni) {
                const int col = c * 64 + pn0 + ni * 8 + 2 * t4;
                float2 o0 = { acc[mi][ni][0], acc[mi][ni][1] };
                float2 o1 = { acc[mi][ni][2], acc[mi][ni][3] };
                *(float2*)(g_accv + nA + col) = o0;
                *(float2*)(g_accv + nB + col) = o1;
            }
        }
        __syncthreads();
    }
}

// ---------------- Kernel 3: row attention pass + combine (per (b,h)) --------
__global__ __launch_bounds__(256, 2) void row_attn(
    const float* __restrict__ x, const float* __restrict__ gammap,
    float* __restrict__ out)
{
    extern __shared__ float sm[];
    uint32_t* Qs  = (uint32_t*)sm;
    uint32_t* Ks  = (uint32_t*)(sm + SM_KS);
    float*    Ps  = sm + SM_PS;
    uint32_t* Psu = (uint32_t*)Ps;
    uint32_t* Vsu = (uint32_t*)sm;
    float* ms = sm + SM_MS;
    float* ls = sm + SM_LS;
    float* fv = sm + SM_FV;
    float* fh = sm + SM_FH;

    const int tid = threadIdx.x;
    const int lane = tid & 31;
    const int warp = tid >> 5;
    const int g8 = lane >> 2, t4 = lane & 3;
    const int b = blockIdx.x / HH;
    const int h = blockIdx.x % HH;
    const int nbase = (b * HH + h) * WW;

    const uint32_t qBase = s2u(Qs), kBase = s2u(Ks), pBase = s2u(Psu), vBase = s2u(Vsu);

    for (int idx = tid; idx < WW * 16; idx += 256) {
        int pos = idx >> 4, c4 = (idx & 15) * 4;
        size_t off = (size_t)(nbase + pos) * DD + c4;
        uint32_t d = (pos * QK_STRIDE + c4) * 4;
        cpa16(qBase + d, g_q + off);
        cpa16(kBase + d, g_k + off);
    }
    if (tid < WW) {
        fv[tid] = g_mv[nbase + tid];
        fh[tid] = g_lv[nbase + tid];
    }
    cpa_commit();
    cpa_wait_all();
    __syncthreads();

    {
        const int sm0 = (warp & 1) * 48, sn0 = (warp >> 1) * 24;
        uint32_t qOff[3];
        #pragma unroll
        for (int mi = 0; mi < 3; ++mi)
            qOff[mi] = ((sm0 + mi * 16 + (lane & 15)) * QK_STRIDE + 4 * (lane >> 4)) * 4;
        const uint32_t kOff01 = ((sn0 + ((lane & 16) >> 1) + (lane & 7)) * QK_STRIDE
                                 + 4 * ((lane >> 3) & 1)) * 4;
        const uint32_t kOff2  = ((sn0 + 16 + (lane & 7)) * QK_STRIDE
                                 + 4 * ((lane >> 3) & 1)) * 4;

        float acc[3][3][4] = {};
        #pragma unroll
        for (int ks = 0; ks < 8; ++ks) {
            const uint32_t kbB = ks * 32;
            uint32_t a[3][4], b01[4], b2[2];
            ldsm4(a[0], qBase + qOff[0] + kbB);
            ldsm4(a[1], qBase + qOff[1] + kbB);
            ldsm4(a[2], qBase + qOff[2] + kbB);
            ldsm4(b01, kBase + kOff01 + kbB);
            ldsm2(b2,  kBase + kOff2  + kbB);
            #pragma unroll
            for (int mi = 0; mi < 3; ++mi) {
                mma_tf32(acc[mi][0], a[mi], b01);
                mma_tf32(acc[mi][1], a[mi], b01 + 2);
                mma_tf32(acc[mi][2], a[mi], b2);
            }
        }

        #pragma unroll
        for (int mi = 0; mi < 3; ++mi) {
            const int r0 = sm0 + mi * 16 + g8, r1 = r0 + 8;
            #pragma unroll
            for (int ni = 0; ni < 3; ++ni) {
                const int c0 = sn0 + ni * 8 + 2 * t4;
                *(float2*)&Ps[r0 * PS_STRIDE + c0] = *(float2*)&acc[mi][ni][0];
                *(float2*)&Ps[r1 * PS_STRIDE + c0] = *(float2*)&acc[mi][ni][2];
            }
        }
    }
    __syncthreads();   // Qs/Ks dead

    {
        for (int idx = tid; idx < WW * 16; idx += 256) {
            int u0 = idx >> 4, c4 = (idx & 15) * 4;
            cpa16(vBase + (u0 * VCH_STRIDE + c4) * 4,
                  g_v + (size_t)(nbase + u0) * CC + c4);
        }
        cpa_commit();
    }

    for (int wq = warp; wq < WW; wq += 8) {
        float m = -3.4e38f;
        for (int g = lane; g < WW; g += 32) m = fmaxf(m, Ps[wq * PS_STRIDE + g]);
        #pragma unroll
        for (int o = 16; o; o >>= 1) m = fmaxf(m, __shfl_xor_sync(0xffffffffu, m, o));
        float l = 0.f;
        for (int g = lane; g < WW; g += 32) {
            uint32_t u = f2tf32(__expf(Ps[wq * PS_STRIDE + g] - m));
            Psu[wq * PS_STRIDE + g] = u;
            l += __uint_as_float(u);
        }
        #pragma unroll
        for (int o = 16; o; o >>= 1) l += __shfl_xor_sync(0xffffffffu, l, o);
        if (lane == 0) { ms[wq] = m; ls[wq] = l; }
    }
    __syncthreads();

    if (tid < WW) {
        float mh = ms[tid], lh = ls[tid];
        float mv = fv[tid], lv = fh[tid];
        float M  = fmaxf(mh, mv);
        float ev = __expf(mv - M), eh = __expf(mh - M);
        float inv = 1.f / (ev * lv + eh * lh);
        fv[tid] = ev * inv;
        fh[tid] = eh * inv;
    }

    const float gamma = *gammap;
    const int pm0 = (warp & 1) * 48, pn0 = (warp >> 1) * 16;
    uint32_t pOff[3];
    #pragma unroll
    for (int mi = 0; mi < 3; ++mi)
        pOff[mi] = ((pm0 + mi * 16 + (lane & 15)) * PS_STRIDE + 4 * (lane >> 4)) * 4;

    for (int c = 0; c < NCHUNK; ++c) {
        if (c + 1 < NCHUNK) {
            const uint32_t dst = vBase + ((c + 1) & 1) * 6528 * 4;
            for (int idx = tid; idx < WW * 16; idx += 256) {
                int u0 = idx >> 4, c4 = (idx & 15) * 4;
                cpa16(dst + (u0 * VCH_STRIDE + c4) * 4,
                      g_v + (size_t)(nbase + u0) * CC + (c + 1) * 64 + c4);
            }
            cpa_commit();
            cpa_wait1();
        } else {
            cpa_wait0();
        }
        __syncthreads();

        float2 pav[3][2][2], pxv[3][2][2];
        #pragma unroll
        for (int mi = 0; mi < 3; ++mi) {
            const int rA = pm0 + mi * 16 + g8;
            const size_t oA = (size_t)(nbase + rA) * CC;
            const size_t oB = (size_t)(nbase + rA + 8) * CC;
            #pragma unroll
            for (int ni = 0; ni < 2; ++ni) {
                const int col = c * 64 + pn0 + ni * 8 + 2 * t4;
                pav[mi][ni][0] = *(const float2*)(g_accv + oA + col);
                pxv[mi][ni][0] = *(const float2*)(x + oA + col);
                pav[mi][ni][1] = *(const float2*)(g_accv + oB + col);
                pxv[mi][ni][1] = *(const float2*)(x + oB + col);
            }
        }

        const uint32_t* Vb = Vsu + (c & 1) * 6528;
        float acc[3][2][4] = {};
        #pragma unroll
        for (int ks = 0; ks < 12; ++ks) {
            const int kb = ks * 8;
            const uint32_t kbB = ks * 32;
            uint32_t a[3][4], bf[2][2];
            ldsm4(a[0], pBase + pOff[0] + kbB);
            ldsm4(a[1], pBase + pOff[1] + kbB);
            ldsm4(a[2], pBase + pOff[2] + kbB);
            #pragma unroll
            for (int ni = 0; ni < 2; ++ni) {
                const int n = pn0 + ni * 8 + g8;
                bf[ni][0] = Vb[(kb + t4    ) * VCH_STRIDE + n];
                bf[ni][1] = Vb[(kb + t4 + 4) * VCH_STRIDE + n];
            }
            #pragma unroll
            for (int mi = 0; mi < 3; ++mi)
                #pragma unroll
                for (int ni = 0; ni < 2; ++ni)
                    mma_tf32(acc[mi][ni], a[mi], bf[ni]);
        }

        #pragma unroll
        for (int mi = 0; mi < 3; ++mi) {
            const int rA = pm0 + mi * 16 + g8;
            const int rB = rA + 8;
            const float fvA = fv[rA], fhA = fh[rA];
            const float fvB = fv[rB], fhB = fh[rB];
            const size_t oA = (size_t)(nbase + rA) * CC;
            const size_t oB = (size_t)(nbase + rB) * CC;
            #pragma unroll
            for (int ni = 0; ni < 2; ++ni) {
                const int col = c * 64 + pn0 + ni * 8 + 2 * t4;
                float2 o0, o1;
                o0.x = pxv[mi][ni][0].x + gamma * (fvA * pav[mi][ni][0].x + fhA * acc[mi][ni][0]);
                o0.y = pxv[mi][ni][0].y + gamma * (fvA * pav[mi][ni][0].y + fhA * acc[mi][ni][1]);
                o1.x = pxv[mi][ni][1].x + gamma * (fvB * pav[mi][ni][1].x + fhB * acc[mi][ni][2]);
                o1.y = pxv[mi][ni][1].y + gamma * (fvB * pav[mi][ni][1].y + fhB * acc[mi][ni][3]);
                *(float2*)(out + oA + col) = o0;
                *(float2*)(out + oB + col) = o1;
            }
        }
        __syncthreads();
    }
}

// ---------------- launch ----------------------------------------------------
extern "C" void kernel_launch(void* const* d_in, const int* in_sizes, int n_in,
                              void* d_out, int out_size)
{
    const float* x  = (const float*)d_in[0];
    const float* Wq = (const float*)d_in[1];
    const float* bq = (const float*)d_in[2];
    const float* Wk = (const float*)d_in[3];
    const float* bk = (const float*)d_in[4];
    const float* Wv = (const float*)d_in[5];
    const float* bv = (const float*)d_in[6];
    const float* gm = (const float*)d_in[7];
    float* out = (float*)d_out;

    cudaFuncSetAttribute(qkv_gemm, cudaFuncAttributeMaxDynamicSharedMemorySize, QKV_SMEM_BYTES);
    cudaFuncSetAttribute(col_attn, cudaFuncAttributeMaxDynamicSharedMemorySize, SMEM_BYTES);
    cudaFuncSetAttribute(row_attn, cudaFuncAttributeMaxDynamicSharedMemorySize, SMEM_BYTES);

    cvt_w<<<1280, 256>>>(Wq, Wk, Wv);
    dim3 gA(5, 576);
    qkv_gemm<<<gA, 256, QKV_SMEM_BYTES>>>(x, bq, bk, bv);
    col_attn<<<768, 256, SMEM_BYTES>>>();
    row_attn<<<768, 256, SMEM_BYTES>>>(x, gm, out);
}